// round 1
// baseline (speedup 1.0000x reference)
#include <cuda_runtime.h>
#include <math.h>

#define S_IMG 4096
#define S_TXT 512
#define S_TOT 4608
#define D_MODEL 3072
#define NH 24
#define NKV 8
#define HD 128

// ---------------- scratch (static device globals; no dynamic alloc) ----------------
__device__ float g_q[NH * S_TOT * HD];    // [h][s][d], joint order: text rows 0..511, image 512..4607
__device__ float g_k[NKV * S_TOT * HD];
__device__ float g_v[NKV * S_TOT * HD];
__device__ float g_o[NH * S_TOT * HD];

// ---------------- generic SGEMM: C = A @ B + bias ----------------
// AMODE 0: A row-major [M,K].  AMODE 1: A gathered from head-major buf [(k>>7)][a_soff+m][k&127]
// CMODE 0: C row-major (ldc = N). CMODE 1: C scattered head-major [(n>>7)][c_soff+m][n&127]
#define BM 128
#define BN 128
#define BK 16

template<int AMODE, int CMODE>
__global__ __launch_bounds__(256) void gemm_k(
    const float* __restrict__ A, const float* __restrict__ B,
    const float* __restrict__ bias, float* __restrict__ C,
    int M, int N, int K, int a_soff, int c_soff)
{
    __shared__ float As[BK][BM];   // transposed A tile
    __shared__ float Bs[BK][BN];
    const int tid = threadIdx.x;
    const int ty = tid >> 4, tx = tid & 15;
    const int m0 = blockIdx.y * BM, n0 = blockIdx.x * BN;

    float acc[8][8];
#pragma unroll
    for (int i = 0; i < 8; i++)
#pragma unroll
        for (int j = 0; j < 8; j++) acc[i][j] = 0.f;

    for (int k0 = 0; k0 < K; k0 += BK) {
        // load A tile (128x16): 512 float4, 2 per thread
#pragma unroll
        for (int i = 0; i < 2; i++) {
            int vv = tid + i * 256;
            int row = vv >> 2;
            int c4 = (vv & 3) << 2;
            int gm = m0 + row, gk = k0 + c4;
            const float* ap;
            if (AMODE == 0) ap = A + (size_t)gm * K + gk;
            else            ap = A + ((size_t)(gk >> 7) * S_TOT + a_soff + gm) * HD + (gk & 127);
            float4 a = *(const float4*)ap;
            As[c4 + 0][row] = a.x; As[c4 + 1][row] = a.y;
            As[c4 + 2][row] = a.z; As[c4 + 3][row] = a.w;
        }
        // load B tile (16x128): 512 float4, 2 per thread (fully coalesced)
#pragma unroll
        for (int i = 0; i < 2; i++) {
            int vv = tid + i * 256;
            int row = vv >> 5;
            int col = (vv & 31) << 2;
            *(float4*)&Bs[row][col] = *(const float4*)(B + (size_t)(k0 + row) * N + n0 + col);
        }
        __syncthreads();
#pragma unroll
        for (int kk = 0; kk < BK; kk++) {
            float4 a0 = *(float4*)&As[kk][ty << 2];
            float4 a1 = *(float4*)&As[kk][64 + (ty << 2)];
            float4 b0 = *(float4*)&Bs[kk][tx << 2];
            float4 b1 = *(float4*)&Bs[kk][64 + (tx << 2)];
            float av[8] = {a0.x, a0.y, a0.z, a0.w, a1.x, a1.y, a1.z, a1.w};
            float bv[8] = {b0.x, b0.y, b0.z, b0.w, b1.x, b1.y, b1.z, b1.w};
#pragma unroll
            for (int i = 0; i < 8; i++)
#pragma unroll
                for (int j = 0; j < 8; j++)
                    acc[i][j] = fmaf(av[i], bv[j], acc[i][j]);
        }
        __syncthreads();
    }
    // epilogue: rows {ty*4+i, 64+ty*4+i}, cols {tx*4+j, 64+tx*4+j}
#pragma unroll
    for (int i = 0; i < 8; i++) {
        int row = m0 + ((i < 4) ? ((ty << 2) + i) : (64 + (ty << 2) + i - 4));
#pragma unroll
        for (int jg = 0; jg < 2; jg++) {
            int col = n0 + jg * 64 + (tx << 2);
            float4 r;
            r.x = acc[i][jg * 4 + 0] + bias[col + 0];
            r.y = acc[i][jg * 4 + 1] + bias[col + 1];
            r.z = acc[i][jg * 4 + 2] + bias[col + 2];
            r.w = acc[i][jg * 4 + 3] + bias[col + 3];
            float* cp;
            if (CMODE == 0) cp = C + (size_t)row * N + col;
            else            cp = C + ((size_t)(col >> 7) * S_TOT + c_soff + row) * HD + (col & 127);
            *(float4*)cp = r;
        }
    }
}

// ---------------- fused RMSNorm + RoPE (one warp per (head, pos) row) ----------------
__global__ void norm_rope_k(float* __restrict__ buf, const float* __restrict__ w,
                            const float* __restrict__ rope, int s0, int scount)
{
    int warp = threadIdx.x >> 5;
    int lane = threadIdx.x & 31;
    int idx = blockIdx.x * 4 + warp;         // idx = h * scount + sl
    int h = idx / scount;
    int sl = idx - h * scount;
    int s = s0 + sl;
    float* row = buf + ((size_t)h * S_TOT + s) * HD;
    float4 x = *(float4*)(row + (lane << 2));
    float ss = x.x * x.x + x.y * x.y + x.z * x.z + x.w * x.w;
#pragma unroll
    for (int o = 16; o; o >>= 1) ss += __shfl_xor_sync(0xffffffffu, ss, o);
    float r = rsqrtf(ss * (1.0f / HD) + 1e-6f);
    float4 wv = *(const float4*)(w + (lane << 2));
    float y0 = x.x * r * wv.x;
    float y1 = x.y * r * wv.y;
    float y2 = x.z * r * wv.z;
    float y3 = x.w * r * wv.w;
    const float* cp = rope + (size_t)s * HD + (lane << 2);
    const float* sp = rope + (size_t)S_TOT * HD + (size_t)s * HD + (lane << 2);
    float4 c = *(const float4*)cp;
    float4 sn = *(const float4*)sp;
    float4 o4;
    o4.x = y0 * c.x - y1 * sn.x;   // even: x0*cos - x1*sin
    o4.y = y1 * c.y + y0 * sn.y;   // odd:  x1*cos + x0*sin
    o4.z = y2 * c.z - y3 * sn.z;
    o4.w = y3 * c.w + y2 * sn.w;
    *(float4*)(row + (lane << 2)) = o4;
}

// ---------------- flash attention (fp32, 64x64 tiles) ----------------
#define AT_BM 64
#define AT_BN 64

struct AttnSmem {
    float Qt[HD][AT_BM];          // Q transposed (scaled)
    float Kt[HD][AT_BN];          // K transposed
    float Vs[AT_BN][HD];
    float Ps[AT_BM][AT_BN + 4];   // padded to kill bank conflicts on column reads
};

__global__ __launch_bounds__(256) void attn_k(
    const float* __restrict__ q, const float* __restrict__ k,
    const float* __restrict__ v, float* __restrict__ o)
{
    extern __shared__ unsigned char smem_raw[];
    AttnSmem& sm = *reinterpret_cast<AttnSmem*>(smem_raw);
    const int tid = threadIdx.x;
    const int ty = tid >> 4, tx = tid & 15;
    const int h = blockIdx.y;
    const int m0 = blockIdx.x * AT_BM;
    const int kvh = h / 3;                    // GQA repeat_interleave: 24 -> 8
    const float scale = 0.088388347648318447f; // 128^-0.5

    // load Q tile transposed, pre-scaled
    const float* qbase = q + ((size_t)h * S_TOT + m0) * HD;
    for (int p = tid; p < AT_BM * (HD / 4); p += 256) {
        int r = p >> 5, c4 = (p & 31) << 2;
        float4 a = *(const float4*)(qbase + r * HD + c4);
        sm.Qt[c4 + 0][r] = a.x * scale;
        sm.Qt[c4 + 1][r] = a.y * scale;
        sm.Qt[c4 + 2][r] = a.z * scale;
        sm.Qt[c4 + 3][r] = a.w * scale;
    }

    float m_i[4], l_i[4], oacc[4][8];
#pragma unroll
    for (int i = 0; i < 4; i++) {
        m_i[i] = -INFINITY; l_i[i] = 0.f;
#pragma unroll
        for (int j = 0; j < 8; j++) oacc[i][j] = 0.f;
    }
    __syncthreads();

    for (int n0 = 0; n0 < S_TOT; n0 += AT_BN) {
        const float* kbase = k + ((size_t)kvh * S_TOT + n0) * HD;
        const float* vbase = v + ((size_t)kvh * S_TOT + n0) * HD;
        for (int p = tid; p < AT_BN * (HD / 4); p += 256) {
            int r = p >> 5, c4 = (p & 31) << 2;
            float4 a = *(const float4*)(kbase + r * HD + c4);
            sm.Kt[c4 + 0][r] = a.x; sm.Kt[c4 + 1][r] = a.y;
            sm.Kt[c4 + 2][r] = a.z; sm.Kt[c4 + 3][r] = a.w;
            *(float4*)&sm.Vs[r][c4] = *(const float4*)(vbase + r * HD + c4);
        }
        __syncthreads();

        // S = Q @ K^T  (thread rows 4ty..4ty+3, cols 4tx..4tx+3)
        float sacc[4][4];
#pragma unroll
        for (int i = 0; i < 4; i++)
#pragma unroll
            for (int j = 0; j < 4; j++) sacc[i][j] = 0.f;
#pragma unroll 8
        for (int kk = 0; kk < HD; kk++) {
            float4 qa = *(float4*)&sm.Qt[kk][ty << 2];
            float4 ka = *(float4*)&sm.Kt[kk][tx << 2];
            float qv[4] = {qa.x, qa.y, qa.z, qa.w};
            float kv2[4] = {ka.x, ka.y, ka.z, ka.w};
#pragma unroll
            for (int i = 0; i < 4; i++)
#pragma unroll
                for (int j = 0; j < 4; j++)
                    sacc[i][j] = fmaf(qv[i], kv2[j], sacc[i][j]);
        }

        // online softmax per row (reduce across the 16 tx lanes)
#pragma unroll
        for (int i = 0; i < 4; i++) {
            float rmax = fmaxf(fmaxf(sacc[i][0], sacc[i][1]), fmaxf(sacc[i][2], sacc[i][3]));
#pragma unroll
            for (int off = 8; off; off >>= 1)
                rmax = fmaxf(rmax, __shfl_xor_sync(0xffffffffu, rmax, off));
            float mnew = fmaxf(m_i[i], rmax);
            float alpha = __expf(m_i[i] - mnew);
            float p0 = __expf(sacc[i][0] - mnew);
            float p1 = __expf(sacc[i][1] - mnew);
            float p2 = __expf(sacc[i][2] - mnew);
            float p3 = __expf(sacc[i][3] - mnew);
            float rs = p0 + p1 + p2 + p3;
#pragma unroll
            for (int off = 8; off; off >>= 1)
                rs += __shfl_xor_sync(0xffffffffu, rs, off);
            l_i[i] = l_i[i] * alpha + rs;
            m_i[i] = mnew;
            float4 pv4 = make_float4(p0, p1, p2, p3);
            *(float4*)&sm.Ps[(ty << 2) + i][tx << 2] = pv4;
#pragma unroll
            for (int j = 0; j < 8; j++) oacc[i][j] *= alpha;
        }
        __syncthreads();

        // O += P @ V  (thread rows 4ty..4ty+3, cols {4tx.., 64+4tx..})
#pragma unroll 4
        for (int j = 0; j < AT_BN; j++) {
            float pr[4];
#pragma unroll
            for (int i = 0; i < 4; i++) pr[i] = sm.Ps[(ty << 2) + i][j];
            float4 v0 = *(float4*)&sm.Vs[j][tx << 2];
            float4 v1 = *(float4*)&sm.Vs[j][64 + (tx << 2)];
#pragma unroll
            for (int i = 0; i < 4; i++) {
                oacc[i][0] = fmaf(pr[i], v0.x, oacc[i][0]);
                oacc[i][1] = fmaf(pr[i], v0.y, oacc[i][1]);
                oacc[i][2] = fmaf(pr[i], v0.z, oacc[i][2]);
                oacc[i][3] = fmaf(pr[i], v0.w, oacc[i][3]);
                oacc[i][4] = fmaf(pr[i], v1.x, oacc[i][4]);
                oacc[i][5] = fmaf(pr[i], v1.y, oacc[i][5]);
                oacc[i][6] = fmaf(pr[i], v1.z, oacc[i][6]);
                oacc[i][7] = fmaf(pr[i], v1.w, oacc[i][7]);
            }
        }
        __syncthreads();
    }

    // write out (normalized)
#pragma unroll
    for (int i = 0; i < 4; i++) {
        float inv = 1.0f / l_i[i];
        int row = m0 + (ty << 2) + i;
        float* ob = o + ((size_t)h * S_TOT + row) * HD;
        float4 r0 = make_float4(oacc[i][0] * inv, oacc[i][1] * inv, oacc[i][2] * inv, oacc[i][3] * inv);
        float4 r1 = make_float4(oacc[i][4] * inv, oacc[i][5] * inv, oacc[i][6] * inv, oacc[i][7] * inv);
        *(float4*)(ob + (tx << 2)) = r0;
        *(float4*)(ob + 64 + (tx << 2)) = r1;
    }
}

// ---------------- launch ----------------
extern "C" void kernel_launch(void* const* d_in, const int* in_sizes, int n_in,
                              void* d_out, int out_size)
{
    const float* hs    = (const float*)d_in[0];
    const float* ehs   = (const float*)d_in[1];
    const float* rope  = (const float*)d_in[2];
    const float* Wq    = (const float*)d_in[3];
    const float* bq    = (const float*)d_in[4];
    const float* Wk    = (const float*)d_in[5];
    const float* bk    = (const float*)d_in[6];
    const float* Wv    = (const float*)d_in[7];
    const float* bv    = (const float*)d_in[8];
    const float* aWq   = (const float*)d_in[9];
    const float* abq   = (const float*)d_in[10];
    const float* aWk   = (const float*)d_in[11];
    const float* abk   = (const float*)d_in[12];
    const float* aWv   = (const float*)d_in[13];
    const float* abv   = (const float*)d_in[14];
    const float* nq    = (const float*)d_in[15];
    const float* nk    = (const float*)d_in[16];
    const float* anq   = (const float*)d_in[17];
    const float* ank   = (const float*)d_in[18];
    const float* Wout  = (const float*)d_in[19];
    const float* bout  = (const float*)d_in[20];
    const float* Waout = (const float*)d_in[21];
    const float* baout = (const float*)d_in[22];
    float* out = (float*)d_out;

    float *q, *k, *v, *o;
    cudaGetSymbolAddress((void**)&q, g_q);
    cudaGetSymbolAddress((void**)&k, g_k);
    cudaGetSymbolAddress((void**)&v, g_v);
    cudaGetSymbolAddress((void**)&o, g_o);

    // image-stream projections (joint rows 512..4607)
    gemm_k<0, 1><<<dim3(D_MODEL / BN, S_IMG / BM), 256>>>(hs, Wq, bq, q, S_IMG, D_MODEL, D_MODEL, 0, S_TXT);
    gemm_k<0, 1><<<dim3((NKV * HD) / BN, S_IMG / BM), 256>>>(hs, Wk, bk, k, S_IMG, NKV * HD, D_MODEL, 0, S_TXT);
    gemm_k<0, 1><<<dim3((NKV * HD) / BN, S_IMG / BM), 256>>>(hs, Wv, bv, v, S_IMG, NKV * HD, D_MODEL, 0, S_TXT);
    // text-stream projections (joint rows 0..511)
    gemm_k<0, 1><<<dim3(D_MODEL / BN, S_TXT / BM), 256>>>(ehs, aWq, abq, q, S_TXT, D_MODEL, D_MODEL, 0, 0);
    gemm_k<0, 1><<<dim3((NKV * HD) / BN, S_TXT / BM), 256>>>(ehs, aWk, abk, k, S_TXT, NKV * HD, D_MODEL, 0, 0);
    gemm_k<0, 1><<<dim3((NKV * HD) / BN, S_TXT / BM), 256>>>(ehs, aWv, abv, v, S_TXT, NKV * HD, D_MODEL, 0, 0);

    // RMSNorm + RoPE (text region uses a-weights; image region uses plain weights)
    norm_rope_k<<<(NH * S_TXT) / 4, 128>>>(q, anq, rope, 0, S_TXT);
    norm_rope_k<<<(NH * S_IMG) / 4, 128>>>(q, nq, rope, S_TXT, S_IMG);
    norm_rope_k<<<(NKV * S_TXT) / 4, 128>>>(k, ank, rope, 0, S_TXT);
    norm_rope_k<<<(NKV * S_IMG) / 4, 128>>>(k, nk, rope, S_TXT, S_IMG);

    // attention
    int smem = (int)sizeof(AttnSmem);
    cudaFuncSetAttribute(attn_k, cudaFuncAttributeMaxDynamicSharedMemorySize, smem);
    attn_k<<<dim3(S_TOT / AT_BM, NH), 256, smem>>>(q, k, v, o);

    // output projections: hid (image rows) first, then enc (text rows)
    gemm_k<1, 0><<<dim3(D_MODEL / BN, S_IMG / BM), 256>>>(o, Wout, bout, out, S_IMG, D_MODEL, NH * HD, S_TXT, 0);
    gemm_k<1, 0><<<dim3(D_MODEL / BN, S_TXT / BM), 256>>>(o, Waout, baout, out + (size_t)S_IMG * D_MODEL, S_TXT, D_MODEL, NH * HD, 0, 0);
}

// round 3
// speedup vs baseline: 4.6854x; 4.6854x over previous
#include <cuda_runtime.h>
#include <cuda_fp16.h>
#include <cstdint>
#include <math.h>

#define S_IMG 4096
#define S_TXT 512
#define S_TOT 4608
#define D_MODEL 3072
#define NH 24
#define NKV 8
#define HD 128

// ---------------- scratch buffers ----------------
// split fp16 inputs (hi/lo)
__device__ __align__(16) __half g_hsh[S_IMG * D_MODEL];
__device__ __align__(16) __half g_hsl[S_IMG * D_MODEL];
__device__ __align__(16) __half g_ehsh[S_TXT * D_MODEL];
__device__ __align__(16) __half g_ehsl[S_TXT * D_MODEL];
__device__ __align__(16) __half g_wqh[D_MODEL * 3072];
__device__ __align__(16) __half g_wql[D_MODEL * 3072];
__device__ __align__(16) __half g_wkh[D_MODEL * 1024];
__device__ __align__(16) __half g_wkl[D_MODEL * 1024];
__device__ __align__(16) __half g_wvh[D_MODEL * 1024];
__device__ __align__(16) __half g_wvl[D_MODEL * 1024];
__device__ __align__(16) __half g_awqh[D_MODEL * 3072];
__device__ __align__(16) __half g_awql[D_MODEL * 3072];
__device__ __align__(16) __half g_awkh[D_MODEL * 1024];
__device__ __align__(16) __half g_awkl[D_MODEL * 1024];
__device__ __align__(16) __half g_awvh[D_MODEL * 1024];
__device__ __align__(16) __half g_awvl[D_MODEL * 1024];
__device__ __align__(16) __half g_wouth[3072 * D_MODEL];
__device__ __align__(16) __half g_woutl[3072 * D_MODEL];
__device__ __align__(16) __half g_waouth[3072 * D_MODEL];
__device__ __align__(16) __half g_waoutl[3072 * D_MODEL];
// q/k pre-norm (f32, head-major joint order)
__device__ __align__(16) float g_qf[NH * S_TOT * HD];
__device__ __align__(16) float g_kf[NKV * S_TOT * HD];
// attention operands (f16, head-major joint order)
__device__ __align__(16) __half g_q[NH * S_TOT * HD];
__device__ __align__(16) __half g_k[NKV * S_TOT * HD];
__device__ __align__(16) __half g_v[NKV * S_TOT * HD];
// attention output, split hi/lo (row-major joint order [S_TOT][3072])
__device__ __align__(16) __half g_oh[S_TOT * 3072];
__device__ __align__(16) __half g_ol[S_TOT * 3072];

// ---------------- PTX helpers ----------------
__device__ __forceinline__ uint32_t cvta_s(const void* p) {
    return (uint32_t)__cvta_generic_to_shared(p);
}
__device__ __forceinline__ void ldsm4(uint32_t* r, uint32_t addr) {
    asm volatile("ldmatrix.sync.aligned.m8n8.x4.shared.b16 {%0,%1,%2,%3},[%4];"
                 : "=r"(r[0]), "=r"(r[1]), "=r"(r[2]), "=r"(r[3]) : "r"(addr));
}
__device__ __forceinline__ void ldsm4t(uint32_t* r, uint32_t addr) {
    asm volatile("ldmatrix.sync.aligned.m8n8.x4.trans.shared.b16 {%0,%1,%2,%3},[%4];"
                 : "=r"(r[0]), "=r"(r[1]), "=r"(r[2]), "=r"(r[3]) : "r"(addr));
}
__device__ __forceinline__ void mma16816(float* c, const uint32_t* a, uint32_t b0, uint32_t b1) {
    asm volatile(
        "mma.sync.aligned.m16n8k16.row.col.f32.f16.f16.f32 "
        "{%0,%1,%2,%3},{%4,%5,%6,%7},{%8,%9},{%0,%1,%2,%3};"
        : "+f"(c[0]), "+f"(c[1]), "+f"(c[2]), "+f"(c[3])
        : "r"(a[0]), "r"(a[1]), "r"(a[2]), "r"(a[3]), "r"(b0), "r"(b1));
}
__device__ __forceinline__ uint32_t packh2(float x, float y) {
    __half2 h = __floats2half2_rn(x, y);
    return *(uint32_t*)&h;
}

// ---------------- fp32 -> split fp16 (hi + lo) ----------------
__global__ void split_k(const float* __restrict__ in, __half* __restrict__ hi,
                        __half* __restrict__ lo, int n) {
    int i = (blockIdx.x * 256 + threadIdx.x) * 4;
    if (i < n) {
        float4 v = *(const float4*)(in + i);
        __half h0 = __float2half_rn(v.x), h1 = __float2half_rn(v.y);
        __half h2 = __float2half_rn(v.z), h3 = __float2half_rn(v.w);
        *(__half2*)(hi + i) = __halves2half2(h0, h1);
        *(__half2*)(hi + i + 2) = __halves2half2(h2, h3);
        *(__half2*)(lo + i) = __floats2half2_rn(v.x - __half2float(h0), v.y - __half2float(h1));
        *(__half2*)(lo + i + 2) = __floats2half2_rn(v.z - __half2float(h2), v.w - __half2float(h3));
    }
}

// ---------------- split HGEMM: C = (Ah+Al)@(Bh+Bl) + bias, 3-term ----------------
// CMODE 0: C row-major f32 (ldc=N). CMODE 1: C head-major f16 scatter.
// CMODE 2: C head-major f32 scatter.
template<int CMODE>
__global__ __launch_bounds__(256) void hsgemm_k(
    const __half* __restrict__ Ah, const __half* __restrict__ Al, int lda, int arow0,
    const __half* __restrict__ Bh, const __half* __restrict__ Bl,
    const float* __restrict__ bias, void* __restrict__ Cp, int N, int K, int c_soff)
{
    __shared__ __align__(16) __half Ash[128 * 32];
    __shared__ __align__(16) __half Asl[128 * 32];
    __shared__ __align__(16) __half Bsh[32 * 128];
    __shared__ __align__(16) __half Bsl[32 * 128];
    const int tid = threadIdx.x;
    const int lane = tid & 31, warp = tid >> 5;
    const int m_off = (warp >> 1) * 32, n_off = (warp & 1) * 64;
    const int m0 = blockIdx.y * 128, n0 = blockIdx.x * 128;

    float c[2][8][4];
#pragma unroll
    for (int mi = 0; mi < 2; mi++)
#pragma unroll
        for (int nj = 0; nj < 8; nj++)
#pragma unroll
            for (int t = 0; t < 4; t++) c[mi][nj][t] = 0.f;

    const int t2 = tid + 256;
    const int aR0 = tid >> 2, aC0 = tid & 3, aR1 = t2 >> 2, aC1 = t2 & 3;
    const int bR0 = tid >> 4, bC0 = tid & 15, bR1 = t2 >> 4, bC1 = t2 & 15;
    const size_t aO0 = (size_t)(arow0 + m0 + aR0) * lda + aC0 * 8;
    const size_t aO1 = (size_t)(arow0 + m0 + aR1) * lda + aC1 * 8;
    const size_t bO0 = (size_t)bR0 * N + n0 + bC0 * 8;
    const size_t bO1 = (size_t)bR1 * N + n0 + bC1 * 8;
    uint4 pA0h = *(const uint4*)(Ah + aO0);
    uint4 pA1h = *(const uint4*)(Ah + aO1);
    uint4 pA0l = *(const uint4*)(Al + aO0);
    uint4 pA1l = *(const uint4*)(Al + aO1);
    uint4 pB0h = *(const uint4*)(Bh + bO0);
    uint4 pB1h = *(const uint4*)(Bh + bO1);
    uint4 pB0l = *(const uint4*)(Bl + bO0);
    uint4 pB1l = *(const uint4*)(Bl + bO1);

    const int sA0 = aR0 * 32 + ((aC0 ^ (aR0 & 3)) << 3);
    const int sA1 = aR1 * 32 + ((aC1 ^ (aR1 & 3)) << 3);
    const int sB0 = bR0 * 128 + ((bC0 ^ (bR0 & 7)) << 3);
    const int sB1 = bR1 * 128 + ((bC1 ^ (bR1 & 7)) << 3);

    const int nkt = K >> 5;
    for (int kt = 0; kt < nkt; kt++) {
        *(uint4*)(Ash + sA0) = pA0h;
        *(uint4*)(Ash + sA1) = pA1h;
        *(uint4*)(Asl + sA0) = pA0l;
        *(uint4*)(Asl + sA1) = pA1l;
        *(uint4*)(Bsh + sB0) = pB0h;
        *(uint4*)(Bsh + sB1) = pB1h;
        *(uint4*)(Bsl + sB0) = pB0l;
        *(uint4*)(Bsl + sB1) = pB1l;
        __syncthreads();
        if (kt + 1 < nkt) {
            int k0 = (kt + 1) << 5;
            pA0h = *(const uint4*)(Ah + aO0 + k0);
            pA1h = *(const uint4*)(Ah + aO1 + k0);
            pA0l = *(const uint4*)(Al + aO0 + k0);
            pA1l = *(const uint4*)(Al + aO1 + k0);
            pB0h = *(const uint4*)(Bh + bO0 + (size_t)k0 * N);
            pB1h = *(const uint4*)(Bh + bO1 + (size_t)k0 * N);
            pB0l = *(const uint4*)(Bl + bO0 + (size_t)k0 * N);
            pB1l = *(const uint4*)(Bl + bO1 + (size_t)k0 * N);
        }
#pragma unroll
        for (int kk = 0; kk < 2; kk++) {
            uint32_t ah[2][4], al[2][4];
#pragma unroll
            for (int mi = 0; mi < 2; mi++) {
                int row = m_off + mi * 16 + (lane & 15);
                int c8 = kk * 2 + (lane >> 4);
                int off = row * 32 + ((c8 ^ (row & 3)) << 3);
                ldsm4(ah[mi], cvta_s(Ash + off));
                ldsm4(al[mi], cvta_s(Asl + off));
            }
#pragma unroll
            for (int njp = 0; njp < 4; njp++) {
                int row = kk * 16 + (lane & 15);
                int c8 = (n_off >> 3) + njp * 2 + (lane >> 4);
                int off = row * 128 + ((c8 ^ (row & 7)) << 3);
                uint32_t bh[4], bl[4];
                ldsm4t(bh, cvta_s(Bsh + off));
                ldsm4t(bl, cvta_s(Bsl + off));
#pragma unroll
                for (int mi = 0; mi < 2; mi++) {
                    mma16816(c[mi][2 * njp], ah[mi], bh[0], bh[1]);
                    mma16816(c[mi][2 * njp], al[mi], bh[0], bh[1]);
                    mma16816(c[mi][2 * njp], ah[mi], bl[0], bl[1]);
                    mma16816(c[mi][2 * njp + 1], ah[mi], bh[2], bh[3]);
                    mma16816(c[mi][2 * njp + 1], al[mi], bh[2], bh[3]);
                    mma16816(c[mi][2 * njp + 1], ah[mi], bl[2], bl[3]);
                }
            }
        }
        __syncthreads();
    }

#pragma unroll
    for (int mi = 0; mi < 2; mi++) {
#pragma unroll
        for (int nj = 0; nj < 8; nj++) {
            int r0 = m0 + m_off + mi * 16 + (lane >> 2);
            int r1 = r0 + 8;
            int col = n0 + n_off + nj * 8 + ((lane & 3) << 1);
            float bx = bias[col], by = bias[col + 1];
            float v00 = c[mi][nj][0] + bx, v01 = c[mi][nj][1] + by;
            float v10 = c[mi][nj][2] + bx, v11 = c[mi][nj][3] + by;
            if (CMODE == 0) {
                float* C = (float*)Cp;
                *(float2*)(C + (size_t)r0 * N + col) = make_float2(v00, v01);
                *(float2*)(C + (size_t)r1 * N + col) = make_float2(v10, v11);
            } else if (CMODE == 1) {
                __half* C = (__half*)Cp;
                int head = col >> 7, hc = col & 127;
                *(__half2*)(C + ((size_t)head * S_TOT + c_soff + r0) * HD + hc) = __floats2half2_rn(v00, v01);
                *(__half2*)(C + ((size_t)head * S_TOT + c_soff + r1) * HD + hc) = __floats2half2_rn(v10, v11);
            } else {
                float* C = (float*)Cp;
                int head = col >> 7, hc = col & 127;
                *(float2*)(C + ((size_t)head * S_TOT + c_soff + r0) * HD + hc) = make_float2(v00, v01);
                *(float2*)(C + ((size_t)head * S_TOT + c_soff + r1) * HD + hc) = make_float2(v10, v11);
            }
        }
    }
}

// ---------------- fused RMSNorm + RoPE (f32 in, f16 out, warp per row) ----------------
__global__ void nr_k(const float* __restrict__ in, __half* __restrict__ outb,
                     const float* __restrict__ w, const float* __restrict__ rope,
                     int s0, int scount, float oscale)
{
    int warp = threadIdx.x >> 5, lane = threadIdx.x & 31;
    int idx = blockIdx.x * 4 + warp;
    int h = idx / scount;
    int s = s0 + (idx - h * scount);
    const float* row = in + ((size_t)h * S_TOT + s) * HD;
    __half* orow = outb + ((size_t)h * S_TOT + s) * HD;
    float4 x = *(const float4*)(row + lane * 4);
    float ss = x.x * x.x + x.y * x.y + x.z * x.z + x.w * x.w;
#pragma unroll
    for (int o = 16; o; o >>= 1) ss += __shfl_xor_sync(0xffffffffu, ss, o);
    float r = rsqrtf(ss * (1.0f / HD) + 1e-6f);
    float4 wv = *(const float4*)(w + lane * 4);
    float y0 = x.x * r * wv.x, y1 = x.y * r * wv.y;
    float y2 = x.z * r * wv.z, y3 = x.w * r * wv.w;
    float4 cc = *(const float4*)(rope + (size_t)s * HD + lane * 4);
    float4 sn = *(const float4*)(rope + (size_t)S_TOT * HD + (size_t)s * HD + lane * 4);
    float o0 = (y0 * cc.x - y1 * sn.x) * oscale;
    float o1 = (y1 * cc.y + y0 * sn.y) * oscale;
    float o2 = (y2 * cc.z - y3 * sn.z) * oscale;
    float o3 = (y3 * cc.w + y2 * sn.w) * oscale;
    *(__half2*)(orow + lane * 4) = __floats2half2_rn(o0, o1);
    *(__half2*)(orow + lane * 4 + 2) = __floats2half2_rn(o2, o3);
}

// ---------------- flash attention (fp16 mma, 64x64 tiles, 4 warps) ----------------
__global__ __launch_bounds__(128) void attn_k(
    const __half* __restrict__ q, const __half* __restrict__ kg,
    const __half* __restrict__ vg, __half* __restrict__ oh, __half* __restrict__ ol)
{
    extern __shared__ __align__(16) __half sm[];
    __half* Qs = sm;
    __half* Ks = sm + 64 * 128;
    __half* Vs = sm + 2 * 64 * 128;
    const int tid = threadIdx.x, lane = tid & 31, w = tid >> 5;
    const int h = blockIdx.y, m0 = blockIdx.x * 64;
    const int kvh = h / 3;

    const __half* qb = q + ((size_t)h * S_TOT + m0) * HD;
#pragma unroll
    for (int t = 0; t < 8; t++) {
        int cid = tid + t * 128;
        int r = cid >> 4, c8 = cid & 15;
        *(uint4*)(Qs + r * 128 + ((c8 ^ (r & 7)) << 3)) =
            *(const uint4*)(qb + (size_t)r * HD + c8 * 8);
    }

    float oa[16][4];
#pragma unroll
    for (int nj = 0; nj < 16; nj++)
#pragma unroll
        for (int t = 0; t < 4; t++) oa[nj][t] = 0.f;
    float mI0 = -INFINITY, mI1 = -INFINITY, lI0 = 0.f, lI1 = 0.f;

    const __half* kb0 = kg + (size_t)kvh * S_TOT * HD;
    const __half* vb0 = vg + (size_t)kvh * S_TOT * HD;

    for (int n0 = 0; n0 < S_TOT; n0 += 64) {
        __syncthreads();
        const __half* kb = kb0 + (size_t)n0 * HD;
        const __half* vb = vb0 + (size_t)n0 * HD;
#pragma unroll
        for (int t = 0; t < 8; t++) {
            int cid = tid + t * 128;
            int r = cid >> 4, c8 = cid & 15;
            int soff = r * 128 + ((c8 ^ (r & 7)) << 3);
            *(uint4*)(Ks + soff) = *(const uint4*)(kb + (size_t)r * HD + c8 * 8);
            *(uint4*)(Vs + soff) = *(const uint4*)(vb + (size_t)r * HD + c8 * 8);
        }
        __syncthreads();

        float s[8][4];
#pragma unroll
        for (int j = 0; j < 8; j++)
#pragma unroll
            for (int t = 0; t < 4; t++) s[j][t] = 0.f;

#pragma unroll
        for (int dk = 0; dk < 8; dk++) {
            uint32_t a[4];
            {
                int row = w * 16 + (lane & 15);
                int c8 = dk * 2 + (lane >> 4);
                ldsm4(a, cvta_s(Qs + row * 128 + ((c8 ^ (row & 7)) << 3)));
            }
#pragma unroll
            for (int njp = 0; njp < 4; njp++) {
                int row = njp * 16 + (lane & 7) + ((lane >> 4) << 3);
                int c8 = dk * 2 + ((lane >> 3) & 1);
                uint32_t b[4];
                ldsm4(b, cvta_s(Ks + row * 128 + ((c8 ^ (row & 7)) << 3)));
                mma16816(s[2 * njp], a, b[0], b[1]);
                mma16816(s[2 * njp + 1], a, b[2], b[3]);
            }
        }

        float mx0 = -INFINITY, mx1 = -INFINITY;
#pragma unroll
        for (int j = 0; j < 8; j++) {
            mx0 = fmaxf(mx0, fmaxf(s[j][0], s[j][1]));
            mx1 = fmaxf(mx1, fmaxf(s[j][2], s[j][3]));
        }
        mx0 = fmaxf(mx0, __shfl_xor_sync(0xffffffffu, mx0, 1));
        mx0 = fmaxf(mx0, __shfl_xor_sync(0xffffffffu, mx0, 2));
        mx1 = fmaxf(mx1, __shfl_xor_sync(0xffffffffu, mx1, 1));
        mx1 = fmaxf(mx1, __shfl_xor_sync(0xffffffffu, mx1, 2));
        float mn0 = fmaxf(mI0, mx0), mn1 = fmaxf(mI1, mx1);
        float al0 = exp2f(mI0 - mn0), al1 = exp2f(mI1 - mn1);
        mI0 = mn0; mI1 = mn1;
        float rs0 = 0.f, rs1 = 0.f;
#pragma unroll
        for (int j = 0; j < 8; j++) {
            s[j][0] = exp2f(s[j][0] - mn0);
            s[j][1] = exp2f(s[j][1] - mn0);
            s[j][2] = exp2f(s[j][2] - mn1);
            s[j][3] = exp2f(s[j][3] - mn1);
            rs0 += s[j][0] + s[j][1];
            rs1 += s[j][2] + s[j][3];
        }
        rs0 += __shfl_xor_sync(0xffffffffu, rs0, 1);
        rs0 += __shfl_xor_sync(0xffffffffu, rs0, 2);
        rs1 += __shfl_xor_sync(0xffffffffu, rs1, 1);
        rs1 += __shfl_xor_sync(0xffffffffu, rs1, 2);
        lI0 = lI0 * al0 + rs0;
        lI1 = lI1 * al1 + rs1;
#pragma unroll
        for (int nj = 0; nj < 16; nj++) {
            oa[nj][0] *= al0; oa[nj][1] *= al0;
            oa[nj][2] *= al1; oa[nj][3] *= al1;
        }
        uint32_t pa[4][4];
#pragma unroll
        for (int kc = 0; kc < 4; kc++) {
            pa[kc][0] = packh2(s[2 * kc][0], s[2 * kc][1]);
            pa[kc][1] = packh2(s[2 * kc][2], s[2 * kc][3]);
            pa[kc][2] = packh2(s[2 * kc + 1][0], s[2 * kc + 1][1]);
            pa[kc][3] = packh2(s[2 * kc + 1][2], s[2 * kc + 1][3]);
        }
#pragma unroll
        for (int kc = 0; kc < 4; kc++) {
#pragma unroll
            for (int njp = 0; njp < 8; njp++) {
                int row = kc * 16 + (lane & 15);
                int c8 = njp * 2 + (lane >> 4);
                uint32_t b[4];
                ldsm4t(b, cvta_s(Vs + row * 128 + ((c8 ^ (row & 7)) << 3)));
                mma16816(oa[2 * njp], pa[kc], b[0], b[1]);
                mma16816(oa[2 * njp + 1], pa[kc], b[2], b[3]);
            }
        }
    }

    float inv0 = 1.f / lI0, inv1 = 1.f / lI1;
    int gr0 = m0 + w * 16 + (lane >> 2);
    int gr1 = gr0 + 8;
#pragma unroll
    for (int nj = 0; nj < 16; nj++) {
        int col = h * 128 + nj * 8 + ((lane & 3) << 1);
        float v00 = oa[nj][0] * inv0, v01 = oa[nj][1] * inv0;
        float v10 = oa[nj][2] * inv1, v11 = oa[nj][3] * inv1;
        __half h00 = __float2half_rn(v00), h01 = __float2half_rn(v01);
        __half h10 = __float2half_rn(v10), h11 = __float2half_rn(v11);
        *(__half2*)(oh + (size_t)gr0 * 3072 + col) = __halves2half2(h00, h01);
        *(__half2*)(oh + (size_t)gr1 * 3072 + col) = __halves2half2(h10, h11);
        *(__half2*)(ol + (size_t)gr0 * 3072 + col) =
            __floats2half2_rn(v00 - __half2float(h00), v01 - __half2float(h01));
        *(__half2*)(ol + (size_t)gr1 * 3072 + col) =
            __floats2half2_rn(v10 - __half2float(h10), v11 - __half2float(h11));
    }
}

// ---------------- launch ----------------
extern "C" void kernel_launch(void* const* d_in, const int* in_sizes, int n_in,
                              void* d_out, int out_size)
{
    const float* hs    = (const float*)d_in[0];
    const float* ehs   = (const float*)d_in[1];
    const float* rope  = (const float*)d_in[2];
    const float* Wq    = (const float*)d_in[3];
    const float* bq    = (const float*)d_in[4];
    const float* Wk    = (const float*)d_in[5];
    const float* bk    = (const float*)d_in[6];
    const float* Wv    = (const float*)d_in[7];
    const float* bv    = (const float*)d_in[8];
    const float* aWq   = (const float*)d_in[9];
    const float* abq   = (const float*)d_in[10];
    const float* aWk   = (const float*)d_in[11];
    const float* abk   = (const float*)d_in[12];
    const float* aWv   = (const float*)d_in[13];
    const float* abv   = (const float*)d_in[14];
    const float* nq    = (const float*)d_in[15];
    const float* nk    = (const float*)d_in[16];
    const float* anq   = (const float*)d_in[17];
    const float* ank   = (const float*)d_in[18];
    const float* Wout  = (const float*)d_in[19];
    const float* bout  = (const float*)d_in[20];
    const float* Waout = (const float*)d_in[21];
    const float* baout = (const float*)d_in[22];
    float* out = (float*)d_out;

    __half *hsh, *hsl, *ehsh, *ehsl;
    __half *wqh, *wql, *wkh, *wkl, *wvh, *wvl;
    __half *awqh, *awql, *awkh, *awkl, *awvh, *awvl;
    __half *wouth, *woutl, *waouth, *waoutl;
    float *qf, *kf;
    __half *q, *k, *v, *oh, *ol;
    cudaGetSymbolAddress((void**)&hsh, g_hsh);
    cudaGetSymbolAddress((void**)&hsl, g_hsl);
    cudaGetSymbolAddress((void**)&ehsh, g_ehsh);
    cudaGetSymbolAddress((void**)&ehsl, g_ehsl);
    cudaGetSymbolAddress((void**)&wqh, g_wqh);
    cudaGetSymbolAddress((void**)&wql, g_wql);
    cudaGetSymbolAddress((void**)&wkh, g_wkh);
    cudaGetSymbolAddress((void**)&wkl, g_wkl);
    cudaGetSymbolAddress((void**)&wvh, g_wvh);
    cudaGetSymbolAddress((void**)&wvl, g_wvl);
    cudaGetSymbolAddress((void**)&awqh, g_awqh);
    cudaGetSymbolAddress((void**)&awql, g_awql);
    cudaGetSymbolAddress((void**)&awkh, g_awkh);
    cudaGetSymbolAddress((void**)&awkl, g_awkl);
    cudaGetSymbolAddress((void**)&awvh, g_awvh);
    cudaGetSymbolAddress((void**)&awvl, g_awvl);
    cudaGetSymbolAddress((void**)&wouth, g_wouth);
    cudaGetSymbolAddress((void**)&woutl, g_woutl);
    cudaGetSymbolAddress((void**)&waouth, g_waouth);
    cudaGetSymbolAddress((void**)&waoutl, g_waoutl);
    cudaGetSymbolAddress((void**)&qf, g_qf);
    cudaGetSymbolAddress((void**)&kf, g_kf);
    cudaGetSymbolAddress((void**)&q, g_q);
    cudaGetSymbolAddress((void**)&k, g_k);
    cudaGetSymbolAddress((void**)&v, g_v);
    cudaGetSymbolAddress((void**)&oh, g_oh);
    cudaGetSymbolAddress((void**)&ol, g_ol);

    // fp32 -> split fp16
    const float* srcs[10] = {hs, ehs, Wq, Wk, Wv, aWq, aWk, aWv, Wout, Waout};
    __half* dh[10] = {hsh, ehsh, wqh, wkh, wvh, awqh, awkh, awvh, wouth, waouth};
    __half* dl[10] = {hsl, ehsl, wql, wkl, wvl, awql, awkl, awvl, woutl, waoutl};
    int ns[10] = {S_IMG * D_MODEL, S_TXT * D_MODEL,
                  D_MODEL * 3072, D_MODEL * 1024, D_MODEL * 1024,
                  D_MODEL * 3072, D_MODEL * 1024, D_MODEL * 1024,
                  3072 * D_MODEL, 3072 * D_MODEL};
    for (int i = 0; i < 10; i++)
        split_k<<<ns[i] / 1024, 256>>>(srcs[i], dh[i], dl[i], ns[i]);

    // projections (image rows -> joint offset 512; text rows -> 0)
    hsgemm_k<2><<<dim3(3072 / 128, S_IMG / 128), 256>>>(hsh, hsl, D_MODEL, 0, wqh, wql, bq, qf, 3072, D_MODEL, S_TXT);
    hsgemm_k<2><<<dim3(1024 / 128, S_IMG / 128), 256>>>(hsh, hsl, D_MODEL, 0, wkh, wkl, bk, kf, 1024, D_MODEL, S_TXT);
    hsgemm_k<1><<<dim3(1024 / 128, S_IMG / 128), 256>>>(hsh, hsl, D_MODEL, 0, wvh, wvl, bv, v, 1024, D_MODEL, S_TXT);
    hsgemm_k<2><<<dim3(3072 / 128, S_TXT / 128), 256>>>(ehsh, ehsl, D_MODEL, 0, awqh, awql, abq, qf, 3072, D_MODEL, 0);
    hsgemm_k<2><<<dim3(1024 / 128, S_TXT / 128), 256>>>(ehsh, ehsl, D_MODEL, 0, awkh, awkl, abk, kf, 1024, D_MODEL, 0);
    hsgemm_k<1><<<dim3(1024 / 128, S_TXT / 128), 256>>>(ehsh, ehsl, D_MODEL, 0, awvh, awvl, abv, v, 1024, D_MODEL, 0);

    // RMSNorm + RoPE (f32 -> f16); fold softmax scale * log2(e) into Q
    const float qscale = 0.08838834764831845f * 1.4426950408889634f;
    nr_k<<<(NH * S_TXT) / 4, 128>>>(qf, q, anq, rope, 0, S_TXT, qscale);
    nr_k<<<(NH * S_IMG) / 4, 128>>>(qf, q, nq, rope, S_TXT, S_IMG, qscale);
    nr_k<<<(NKV * S_TXT) / 4, 128>>>(kf, k, ank, rope, 0, S_TXT, 1.0f);
    nr_k<<<(NKV * S_IMG) / 4, 128>>>(kf, k, nk, rope, S_TXT, S_IMG, 1.0f);

    // attention
    int smem = 3 * 64 * 128 * (int)sizeof(__half);
    cudaFuncSetAttribute(attn_k, cudaFuncAttributeMaxDynamicSharedMemorySize, smem);
    attn_k<<<dim3(S_TOT / 64, NH), 128, smem>>>(q, k, v, oh, ol);

    // output projections: hid (image rows, joint offset 512) then enc (text rows)
    hsgemm_k<0><<<dim3(3072 / 128, S_IMG / 128), 256>>>(oh, ol, 3072, S_TXT, wouth, woutl, bout, out, 3072, 3072, 0);
    hsgemm_k<0><<<dim3(3072 / 128, S_TXT / 128), 256>>>(oh, ol, 3072, 0, waouth, waoutl, baout, out + (size_t)S_IMG * 3072, 3072, 3072, 0);
}

// round 5
// speedup vs baseline: 4.9611x; 1.0588x over previous
#include <cuda_runtime.h>
#include <cuda_fp16.h>
#include <cstdint>
#include <math.h>

#define S_IMG 4096
#define S_TXT 512
#define S_TOT 4608
#define D_MODEL 3072
#define NH 24
#define NKV 8
#define HD 128

// ---------------- scratch buffers ----------------
__device__ __align__(16) __half g_hsh[S_IMG * D_MODEL];
__device__ __align__(16) __half g_hsl[S_IMG * D_MODEL];
__device__ __align__(16) __half g_ehsh[S_TXT * D_MODEL];
__device__ __align__(16) __half g_ehsl[S_TXT * D_MODEL];
__device__ __align__(16) __half g_wqh[D_MODEL * 3072];
__device__ __align__(16) __half g_wql[D_MODEL * 3072];
__device__ __align__(16) __half g_wkh[D_MODEL * 1024];
__device__ __align__(16) __half g_wkl[D_MODEL * 1024];
__device__ __align__(16) __half g_wvh[D_MODEL * 1024];
__device__ __align__(16) __half g_wvl[D_MODEL * 1024];
__device__ __align__(16) __half g_awqh[D_MODEL * 3072];
__device__ __align__(16) __half g_awql[D_MODEL * 3072];
__device__ __align__(16) __half g_awkh[D_MODEL * 1024];
__device__ __align__(16) __half g_awkl[D_MODEL * 1024];
__device__ __align__(16) __half g_awvh[D_MODEL * 1024];
__device__ __align__(16) __half g_awvl[D_MODEL * 1024];
__device__ __align__(16) __half g_wouth[3072 * D_MODEL];
__device__ __align__(16) __half g_woutl[3072 * D_MODEL];
__device__ __align__(16) __half g_waouth[3072 * D_MODEL];
__device__ __align__(16) __half g_waoutl[3072 * D_MODEL];
__device__ __align__(16) float g_qf[NH * S_TOT * HD];
__device__ __align__(16) float g_kf[NKV * S_TOT * HD];
__device__ __align__(16) __half g_q[NH * S_TOT * HD];
__device__ __align__(16) __half g_k[NKV * S_TOT * HD];
__device__ __align__(16) __half g_v[NKV * S_TOT * HD];
__device__ __align__(16) __half g_oh[S_TOT * 3072];
__device__ __align__(16) __half g_ol[S_TOT * 3072];

// ---------------- PTX helpers ----------------
__device__ __forceinline__ uint32_t cvta_s(const void* p) {
    return (uint32_t)__cvta_generic_to_shared(p);
}
__device__ __forceinline__ void ldsm4(uint32_t* r, uint32_t addr) {
    asm volatile("ldmatrix.sync.aligned.m8n8.x4.shared.b16 {%0,%1,%2,%3},[%4];"
                 : "=r"(r[0]), "=r"(r[1]), "=r"(r[2]), "=r"(r[3]) : "r"(addr));
}
__device__ __forceinline__ void ldsm4t(uint32_t* r, uint32_t addr) {
    asm volatile("ldmatrix.sync.aligned.m8n8.x4.trans.shared.b16 {%0,%1,%2,%3},[%4];"
                 : "=r"(r[0]), "=r"(r[1]), "=r"(r[2]), "=r"(r[3]) : "r"(addr));
}
__device__ __forceinline__ void mma16816(float* c, const uint32_t* a, uint32_t b0, uint32_t b1) {
    asm volatile(
        "mma.sync.aligned.m16n8k16.row.col.f32.f16.f16.f32 "
        "{%0,%1,%2,%3},{%4,%5,%6,%7},{%8,%9},{%0,%1,%2,%3};"
        : "+f"(c[0]), "+f"(c[1]), "+f"(c[2]), "+f"(c[3])
        : "r"(a[0]), "r"(a[1]), "r"(a[2]), "r"(a[3]), "r"(b0), "r"(b1));
}
__device__ __forceinline__ uint32_t packh2(float x, float y) {
    __half2 h = __floats2half2_rn(x, y);
    return *(uint32_t*)&h;
}
__device__ __forceinline__ void cp16(uint32_t s, const void* g) {
    asm volatile("cp.async.cg.shared.global [%0], [%1], 16;" :: "r"(s), "l"(g));
}
__device__ __forceinline__ void cp_commit() {
    asm volatile("cp.async.commit_group;" ::: "memory");
}

// ---------------- fp32 -> split fp16 (hi + lo) ----------------
__global__ void split_k(const float* __restrict__ in, __half* __restrict__ hi,
                        __half* __restrict__ lo, int n) {
    int i = (blockIdx.x * 256 + threadIdx.x) * 4;
    if (i < n) {
        float4 v = *(const float4*)(in + i);
        __half h0 = __float2half_rn(v.x), h1 = __float2half_rn(v.y);
        __half h2 = __float2half_rn(v.z), h3 = __float2half_rn(v.w);
        *(__half2*)(hi + i) = __halves2half2(h0, h1);
        *(__half2*)(hi + i + 2) = __halves2half2(h2, h3);
        *(__half2*)(lo + i) = __floats2half2_rn(v.x - __half2float(h0), v.y - __half2float(h1));
        *(__half2*)(lo + i + 2) = __floats2half2_rn(v.z - __half2float(h2), v.w - __half2float(h3));
    }
}

// ---------------- split HGEMM, 3-stage cp.async pipeline ----------------
// Stage layout (halves): Ah[0,4096) Al[4096,8192) Bh[8192,12288) Bl[12288,16384)
#define GS_STAGE 16384
#define GS_BYTES (3 * GS_STAGE * 2)

template<int CMODE>
__global__ __launch_bounds__(256) void hsgemm_k(
    const __half* __restrict__ Ah, const __half* __restrict__ Al, int lda, int arow0,
    const __half* __restrict__ Bh, const __half* __restrict__ Bl,
    const float* __restrict__ bias, void* __restrict__ Cp, int N, int K, int c_soff)
{
    extern __shared__ __align__(16) __half smp[];
    const int tid = threadIdx.x;
    const int lane = tid & 31, warp = tid >> 5;
    const int m_off = (warp >> 1) * 32, n_off = (warp & 1) * 64;
    const int m0 = blockIdx.y * 128, n0 = blockIdx.x * 128;

    float c[2][8][4];
#pragma unroll
    for (int mi = 0; mi < 2; mi++)
#pragma unroll
        for (int nj = 0; nj < 8; nj++)
#pragma unroll
            for (int t = 0; t < 4; t++) c[mi][nj][t] = 0.f;

    const int t2 = tid + 256;
    const int aR0 = tid >> 2, aC0 = tid & 3, aR1 = t2 >> 2, aC1 = t2 & 3;
    const int bR0 = tid >> 4, bC0 = tid & 15, bR1 = t2 >> 4, bC1 = t2 & 15;
    const size_t aO0 = (size_t)(arow0 + m0 + aR0) * lda + aC0 * 8;
    const size_t aO1 = (size_t)(arow0 + m0 + aR1) * lda + aC1 * 8;
    const size_t bO0 = (size_t)bR0 * N + n0 + bC0 * 8;
    const size_t bO1 = (size_t)bR1 * N + n0 + bC1 * 8;
    const int sA0 = aR0 * 32 + ((aC0 ^ (aR0 & 3)) << 3);
    const int sA1 = aR1 * 32 + ((aC1 ^ (aR1 & 3)) << 3);
    const int sB0 = bR0 * 128 + ((bC0 ^ (bR0 & 7)) << 3);
    const int sB1 = bR1 * 128 + ((bC1 ^ (bR1 & 7)) << 3);

    auto issue = [&](int stage, int k0) {
        __half* st = smp + stage * GS_STAGE;
        uint32_t a0 = cvta_s(st + sA0), a1 = cvta_s(st + sA1);
        cp16(a0, Ah + aO0 + k0);
        cp16(a1, Ah + aO1 + k0);
        cp16(a0 + 8192, Al + aO0 + k0);
        cp16(a1 + 8192, Al + aO1 + k0);
        uint32_t b0 = cvta_s(st + 8192 + sB0), b1 = cvta_s(st + 8192 + sB1);
        size_t ko = (size_t)k0 * N;
        cp16(b0, Bh + bO0 + ko);
        cp16(b1, Bh + bO1 + ko);
        cp16(b0 + 8192, Bl + bO0 + ko);
        cp16(b1 + 8192, Bl + bO1 + ko);
    };

    const int nkt = K >> 5;
    issue(0, 0); cp_commit();
    issue(1, 32); cp_commit();

    for (int kt = 0; kt < nkt; kt++) {
        asm volatile("cp.async.wait_group 1;" ::: "memory");
        __syncthreads();
        if (kt + 2 < nkt) issue((kt + 2) % 3, (kt + 2) * 32);
        cp_commit();

        __half* st = smp + (kt % 3) * GS_STAGE;
        __half* Ash = st;
        __half* Asl = st + 4096;
        __half* Bsh = st + 8192;
        __half* Bsl = st + 12288;
#pragma unroll
        for (int kk = 0; kk < 2; kk++) {
            uint32_t ah[2][4], al[2][4];
#pragma unroll
            for (int mi = 0; mi < 2; mi++) {
                int row = m_off + mi * 16 + (lane & 15);
                int c8 = kk * 2 + (lane >> 4);
                int off = row * 32 + ((c8 ^ (row & 3)) << 3);
                ldsm4(ah[mi], cvta_s(Ash + off));
                ldsm4(al[mi], cvta_s(Asl + off));
            }
#pragma unroll
            for (int njp = 0; njp < 4; njp++) {
                int row = kk * 16 + (lane & 15);
                int c8 = (n_off >> 3) + njp * 2 + (lane >> 4);
                int off = row * 128 + ((c8 ^ (row & 7)) << 3);
                uint32_t bh[4], bl[4];
                ldsm4t(bh, cvta_s(Bsh + off));
                ldsm4t(bl, cvta_s(Bsl + off));
#pragma unroll
                for (int mi = 0; mi < 2; mi++) {
                    mma16816(c[mi][2 * njp], ah[mi], bh[0], bh[1]);
                    mma16816(c[mi][2 * njp], al[mi], bh[0], bh[1]);
                    mma16816(c[mi][2 * njp], ah[mi], bl[0], bl[1]);
                    mma16816(c[mi][2 * njp + 1], ah[mi], bh[2], bh[3]);
                    mma16816(c[mi][2 * njp + 1], al[mi], bh[2], bh[3]);
                    mma16816(c[mi][2 * njp + 1], ah[mi], bl[2], bl[3]);
                }
            }
        }
    }

#pragma unroll
    for (int mi = 0; mi < 2; mi++) {
#pragma unroll
        for (int nj = 0; nj < 8; nj++) {
            int r0 = m0 + m_off + mi * 16 + (lane >> 2);
            int r1 = r0 + 8;
            int col = n0 + n_off + nj * 8 + ((lane & 3) << 1);
            float bx = bias[col], by = bias[col + 1];
            float v00 = c[mi][nj][0] + bx, v01 = c[mi][nj][1] + by;
            float v10 = c[mi][nj][2] + bx, v11 = c[mi][nj][3] + by;
            if (CMODE == 0) {
                float* C = (float*)Cp;
                *(float2*)(C + (size_t)r0 * N + col) = make_float2(v00, v01);
                *(float2*)(C + (size_t)r1 * N + col) = make_float2(v10, v11);
            } else if (CMODE == 1) {
                __half* C = (__half*)Cp;
                int head = col >> 7, hc = col & 127;
                *(__half2*)(C + ((size_t)head * S_TOT + c_soff + r0) * HD + hc) = __floats2half2_rn(v00, v01);
                *(__half2*)(C + ((size_t)head * S_TOT + c_soff + r1) * HD + hc) = __floats2half2_rn(v10, v11);
            } else {
                float* C = (float*)Cp;
                int head = col >> 7, hc = col & 127;
                *(float2*)(C + ((size_t)head * S_TOT + c_soff + r0) * HD + hc) = make_float2(v00, v01);
                *(float2*)(C + ((size_t)head * S_TOT + c_soff + r1) * HD + hc) = make_float2(v10, v11);
            }
        }
    }
}

// ---------------- fused RMSNorm + RoPE (f32 in, f16 out, warp per row) ----------------
__global__ void nr_k(const float* __restrict__ in, __half* __restrict__ outb,
                     const float* __restrict__ w, const float* __restrict__ rope,
                     int s0, int scount, float oscale)
{
    int warp = threadIdx.x >> 5, lane = threadIdx.x & 31;
    int idx = blockIdx.x * 4 + warp;
    int h = idx / scount;
    int s = s0 + (idx - h * scount);
    const float* row = in + ((size_t)h * S_TOT + s) * HD;
    __half* orow = outb + ((size_t)h * S_TOT + s) * HD;
    float4 x = *(const float4*)(row + lane * 4);
    float ss = x.x * x.x + x.y * x.y + x.z * x.z + x.w * x.w;
#pragma unroll
    for (int o = 16; o; o >>= 1) ss += __shfl_xor_sync(0xffffffffu, ss, o);
    float r = rsqrtf(ss * (1.0f / HD) + 1e-6f);
    float4 wv = *(const float4*)(w + lane * 4);
    float y0 = x.x * r * wv.x, y1 = x.y * r * wv.y;
    float y2 = x.z * r * wv.z, y3 = x.w * r * wv.w;
    float4 cc = *(const float4*)(rope + (size_t)s * HD + lane * 4);
    float4 sn = *(const float4*)(rope + (size_t)S_TOT * HD + (size_t)s * HD + lane * 4);
    float o0 = (y0 * cc.x - y1 * sn.x) * oscale;
    float o1 = (y1 * cc.y + y0 * sn.y) * oscale;
    float o2 = (y2 * cc.z - y3 * sn.z) * oscale;
    float o3 = (y3 * cc.w + y2 * sn.w) * oscale;
    *(__half2*)(orow + lane * 4) = __floats2half2_rn(o0, o1);
    *(__half2*)(orow + lane * 4 + 2) = __floats2half2_rn(o2, o3);
}

// ---------------- flash attention: 256 thr, 128-row tile, double-buffered cp.async ----------------
#define AT_STEPS (S_TOT / 64)
#define AT_SMEM ((16384 + 2 * 8192 + 2 * 8192) * 2)

__global__ __launch_bounds__(256) void attn_k(
    const __half* __restrict__ q, const __half* __restrict__ kg,
    const __half* __restrict__ vg, __half* __restrict__ oh, __half* __restrict__ ol)
{
    extern __shared__ __align__(16) __half sm[];
    __half* Qs = sm;                 // 128x128
    __half* Kb = sm + 16384;         // 2 x 64x128
    __half* Vb = sm + 32768;         // 2 x 64x128
    const int tid = threadIdx.x, lane = tid & 31, w = tid >> 5;
    const int h = blockIdx.y, m0 = blockIdx.x * 128;
    const int kvh = h / 3;

    const __half* qb = q + ((size_t)h * S_TOT + m0) * HD;
#pragma unroll
    for (int t = 0; t < 8; t++) {
        int cid = tid + t * 256;
        int r = cid >> 4, c8 = cid & 15;
        cp16(cvta_s(Qs + r * 128 + ((c8 ^ (r & 7)) << 3)),
             qb + (size_t)r * HD + c8 * 8);
    }

    const __half* kb0 = kg + (size_t)kvh * S_TOT * HD;
    const __half* vb0 = vg + (size_t)kvh * S_TOT * HD;
    auto issue_kv = [&](int n, int buf) {
        const __half* kb = kb0 + (size_t)n * 64 * HD;
        const __half* vb = vb0 + (size_t)n * 64 * HD;
        __half* Kd = Kb + buf * 8192;
        __half* Vd = Vb + buf * 8192;
#pragma unroll
        for (int t = 0; t < 4; t++) {
            int cid = tid + t * 256;
            int r = cid >> 4, c8 = cid & 15;
            int off = r * 128 + ((c8 ^ (r & 7)) << 3);
            cp16(cvta_s(Kd + off), kb + (size_t)r * HD + c8 * 8);
            cp16(cvta_s(Vd + off), vb + (size_t)r * HD + c8 * 8);
        }
    };
    issue_kv(0, 0);
    cp_commit();

    float oa[16][4];
#pragma unroll
    for (int nj = 0; nj < 16; nj++)
#pragma unroll
        for (int t = 0; t < 4; t++) oa[nj][t] = 0.f;
    float mI0 = -INFINITY, mI1 = -INFINITY, lI0 = 0.f, lI1 = 0.f;

    for (int it = 0; it < AT_STEPS; it++) {
        asm volatile("cp.async.wait_group 0;" ::: "memory");
        __syncthreads();
        if (it + 1 < AT_STEPS) issue_kv(it + 1, (it + 1) & 1);
        cp_commit();
        __half* Ks = Kb + (it & 1) * 8192;
        __half* Vs = Vb + (it & 1) * 8192;

        float s[8][4];
#pragma unroll
        for (int j = 0; j < 8; j++)
#pragma unroll
            for (int t = 0; t < 4; t++) s[j][t] = 0.f;

#pragma unroll
        for (int dk = 0; dk < 8; dk++) {
            uint32_t a[4];
            {
                int row = w * 16 + (lane & 15);
                int c8 = dk * 2 + (lane >> 4);
                ldsm4(a, cvta_s(Qs + row * 128 + ((c8 ^ (row & 7)) << 3)));
            }
#pragma unroll
            for (int njp = 0; njp < 4; njp++) {
                int row = njp * 16 + (lane & 7) + ((lane >> 4) << 3);
                int c8 = dk * 2 + ((lane >> 3) & 1);
                uint32_t b[4];
                ldsm4(b, cvta_s(Ks + row * 128 + ((c8 ^ (row & 7)) << 3)));
                mma16816(s[2 * njp], a, b[0], b[1]);
                mma16816(s[2 * njp + 1], a, b[2], b[3]);
            }
        }

        float mx0 = -INFINITY, mx1 = -INFINITY;
#pragma unroll
        for (int j = 0; j < 8; j++) {
            mx0 = fmaxf(mx0, fmaxf(s[j][0], s[j][1]));
            mx1 = fmaxf(mx1, fmaxf(s[j][2], s[j][3]));
        }
        mx0 = fmaxf(mx0, __shfl_xor_sync(0xffffffffu, mx0, 1));
        mx0 = fmaxf(mx0, __shfl_xor_sync(0xffffffffu, mx0, 2));
        mx1 = fmaxf(mx1, __shfl_xor_sync(0xffffffffu, mx1, 1));
        mx1 = fmaxf(mx1, __shfl_xor_sync(0xffffffffu, mx1, 2));
        float mn0 = fmaxf(mI0, mx0), mn1 = fmaxf(mI1, mx1);
        float al0 = exp2f(mI0 - mn0), al1 = exp2f(mI1 - mn1);
        mI0 = mn0; mI1 = mn1;
        float rs0 = 0.f, rs1 = 0.f;
#pragma unroll
        for (int j = 0; j < 8; j++) {
            s[j][0] = exp2f(s[j][0] - mn0);
            s[j][1] = exp2f(s[j][1] - mn0);
            s[j][2] = exp2f(s[j][2] - mn1);
            s[j][3] = exp2f(s[j][3] - mn1);
            rs0 += s[j][0] + s[j][1];
            rs1 += s[j][2] + s[j][3];
        }
        rs0 += __shfl_xor_sync(0xffffffffu, rs0, 1);
        rs0 += __shfl_xor_sync(0xffffffffu, rs0, 2);
        rs1 += __shfl_xor_sync(0xffffffffu, rs1, 1);
        rs1 += __shfl_xor_sync(0xffffffffu, rs1, 2);
        lI0 = lI0 * al0 + rs0;
        lI1 = lI1 * al1 + rs1;
#pragma unroll
        for (int nj = 0; nj < 16; nj++) {
            oa[nj][0] *= al0; oa[nj][1] *= al0;
            oa[nj][2] *= al1; oa[nj][3] *= al1;
        }
        uint32_t pa[4][4];
#pragma unroll
        for (int kc = 0; kc < 4; kc++) {
            pa[kc][0] = packh2(s[2 * kc][0], s[2 * kc][1]);
            pa[kc][1] = packh2(s[2 * kc][2], s[2 * kc][3]);
            pa[kc][2] = packh2(s[2 * kc + 1][0], s[2 * kc + 1][1]);
            pa[kc][3] = packh2(s[2 * kc + 1][2], s[2 * kc + 1][3]);
        }
#pragma unroll
        for (int kc = 0; kc < 4; kc++) {
#pragma unroll
            for (int njp = 0; njp < 8; njp++) {
                int row = kc * 16 + (lane & 15);
                int c8 = njp * 2 + (lane >> 4);
                uint32_t b[4];
                ldsm4t(b, cvta_s(Vs + row * 128 + ((c8 ^ (row & 7)) << 3)));
                mma16816(oa[2 * njp], pa[kc], b[0], b[1]);
                mma16816(oa[2 * njp + 1], pa[kc], b[2], b[3]);
            }
        }
    }

    float inv0 = 1.f / lI0, inv1 = 1.f / lI1;
    int gr0 = m0 + w * 16 + (lane >> 2);
    int gr1 = gr0 + 8;
#pragma unroll
    for (int nj = 0; nj < 16; nj++) {
        int col = h * 128 + nj * 8 + ((lane & 3) << 1);
        float v00 = oa[nj][0] * inv0, v01 = oa[nj][1] * inv0;
        float v10 = oa[nj][2] * inv1, v11 = oa[nj][3] * inv1;
        __half h00 = __float2half_rn(v00), h01 = __float2half_rn(v01);
        __half h10 = __float2half_rn(v10), h11 = __float2half_rn(v11);
        *(__half2*)(oh + (size_t)gr0 * 3072 + col) = __halves2half2(h00, h01);
        *(__half2*)(oh + (size_t)gr1 * 3072 + col) = __halves2half2(h10, h11);
        *(__half2*)(ol + (size_t)gr0 * 3072 + col) =
            __floats2half2_rn(v00 - __half2float(h00), v01 - __half2float(h01));
        *(__half2*)(ol + (size_t)gr1 * 3072 + col) =
            __floats2half2_rn(v10 - __half2float(h10), v11 - __half2float(h11));
    }
}

// ---------------- launch ----------------
extern "C" void kernel_launch(void* const* d_in, const int* in_sizes, int n_in,
                              void* d_out, int out_size)
{
    const float* hs    = (const float*)d_in[0];
    const float* ehs   = (const float*)d_in[1];
    const float* rope  = (const float*)d_in[2];
    const float* Wq    = (const float*)d_in[3];
    const float* bq    = (const float*)d_in[4];
    const float* Wk    = (const float*)d_in[5];
    const float* bk    = (const float*)d_in[6];
    const float* Wv    = (const float*)d_in[7];
    const float* bv    = (const float*)d_in[8];
    const float* aWq   = (const float*)d_in[9];
    const float* abq   = (const float*)d_in[10];
    const float* aWk   = (const float*)d_in[11];
    const float* abk   = (const float*)d_in[12];
    const float* aWv   = (const float*)d_in[13];
    const float* abv   = (const float*)d_in[14];
    const float* nq    = (const float*)d_in[15];
    const float* nk    = (const float*)d_in[16];
    const float* anq   = (const float*)d_in[17];
    const float* ank   = (const float*)d_in[18];
    const float* Wout  = (const float*)d_in[19];
    const float* bout  = (const float*)d_in[20];
    const float* Waout = (const float*)d_in[21];
    const float* baout = (const float*)d_in[22];
    float* out = (float*)d_out;

    __half *hsh, *hsl, *ehsh, *ehsl;
    __half *wqh, *wql, *wkh, *wkl, *wvh, *wvl;
    __half *awqh, *awql, *awkh, *awkl, *awvh, *awvl;
    __half *wouth, *woutl, *waouth, *waoutl;
    float *qf, *kf;
    __half *q, *k, *v, *oh, *ol;
    cudaGetSymbolAddress((void**)&hsh, g_hsh);
    cudaGetSymbolAddress((void**)&hsl, g_hsl);
    cudaGetSymbolAddress((void**)&ehsh, g_ehsh);
    cudaGetSymbolAddress((void**)&ehsl, g_ehsl);
    cudaGetSymbolAddress((void**)&wqh, g_wqh);
    cudaGetSymbolAddress((void**)&wql, g_wql);
    cudaGetSymbolAddress((void**)&wkh, g_wkh);
    cudaGetSymbolAddress((void**)&wkl, g_wkl);
    cudaGetSymbolAddress((void**)&wvh, g_wvh);
    cudaGetSymbolAddress((void**)&wvl, g_wvl);
    cudaGetSymbolAddress((void**)&awqh, g_awqh);
    cudaGetSymbolAddress((void**)&awql, g_awql);
    cudaGetSymbolAddress((void**)&awkh, g_awkh);
    cudaGetSymbolAddress((void**)&awkl, g_awkl);
    cudaGetSymbolAddress((void**)&awvh, g_awvh);
    cudaGetSymbolAddress((void**)&awvl, g_awvl);
    cudaGetSymbolAddress((void**)&wouth, g_wouth);
    cudaGetSymbolAddress((void**)&woutl, g_woutl);
    cudaGetSymbolAddress((void**)&waouth, g_waouth);
    cudaGetSymbolAddress((void**)&waoutl, g_waoutl);
    cudaGetSymbolAddress((void**)&qf, g_qf);
    cudaGetSymbolAddress((void**)&kf, g_kf);
    cudaGetSymbolAddress((void**)&q, g_q);
    cudaGetSymbolAddress((void**)&k, g_k);
    cudaGetSymbolAddress((void**)&v, g_v);
    cudaGetSymbolAddress((void**)&oh, g_oh);
    cudaGetSymbolAddress((void**)&ol, g_ol);

    // fp32 -> split fp16
    const float* srcs[10] = {hs, ehs, Wq, Wk, Wv, aWq, aWk, aWv, Wout, Waout};
    __half* dh[10] = {hsh, ehsh, wqh, wkh, wvh, awqh, awkh, awvh, wouth, waouth};
    __half* dl[10] = {hsl, ehsl, wql, wkl, wvl, awql, awkl, awvl, woutl, waoutl};
    int ns[10] = {S_IMG * D_MODEL, S_TXT * D_MODEL,
                  D_MODEL * 3072, D_MODEL * 1024, D_MODEL * 1024,
                  D_MODEL * 3072, D_MODEL * 1024, D_MODEL * 1024,
                  3072 * D_MODEL, 3072 * D_MODEL};
    for (int i = 0; i < 10; i++)
        split_k<<<ns[i] / 1024, 256>>>(srcs[i], dh[i], dl[i], ns[i]);

    cudaFuncSetAttribute(hsgemm_k<0>, cudaFuncAttributeMaxDynamicSharedMemorySize, GS_BYTES);
    cudaFuncSetAttribute(hsgemm_k<1>, cudaFuncAttributeMaxDynamicSharedMemorySize, GS_BYTES);
    cudaFuncSetAttribute(hsgemm_k<2>, cudaFuncAttributeMaxDynamicSharedMemorySize, GS_BYTES);

    // projections (image rows -> joint offset 512; text rows -> 0)
    hsgemm_k<2><<<dim3(3072 / 128, S_IMG / 128), 256, GS_BYTES>>>(hsh, hsl, D_MODEL, 0, wqh, wql, bq, qf, 3072, D_MODEL, S_TXT);
    hsgemm_k<2><<<dim3(1024 / 128, S_IMG / 128), 256, GS_BYTES>>>(hsh, hsl, D_MODEL, 0, wkh, wkl, bk, kf, 1024, D_MODEL, S_TXT);
    hsgemm_k<1><<<dim3(1024 / 128, S_IMG / 128), 256, GS_BYTES>>>(hsh, hsl, D_MODEL, 0, wvh, wvl, bv, v, 1024, D_MODEL, S_TXT);
    hsgemm_k<2><<<dim3(3072 / 128, S_TXT / 128), 256, GS_BYTES>>>(ehsh, ehsl, D_MODEL, 0, awqh, awql, abq, qf, 3072, D_MODEL, 0);
    hsgemm_k<2><<<dim3(1024 / 128, S_TXT / 128), 256, GS_BYTES>>>(ehsh, ehsl, D_MODEL, 0, awkh, awkl, abk, kf, 1024, D_MODEL, 0);
    hsgemm_k<1><<<dim3(1024 / 128, S_TXT / 128), 256, GS_BYTES>>>(ehsh, ehsl, D_MODEL, 0, awvh, awvl, abv, v, 1024, D_MODEL, 0);

    // RMSNorm + RoPE (f32 -> f16); fold softmax scale * log2(e) into Q
    const float qscale = 0.08838834764831845f * 1.4426950408889634f;
    nr_k<<<(NH * S_TXT) / 4, 128>>>(qf, q, anq, rope, 0, S_TXT, qscale);
    nr_k<<<(NH * S_IMG) / 4, 128>>>(qf, q, nq, rope, S_TXT, S_IMG, qscale);
    nr_k<<<(NKV * S_TXT) / 4, 128>>>(kf, k, ank, rope, 0, S_TXT, 1.0f);
    nr_k<<<(NKV * S_IMG) / 4, 128>>>(kf, k, nk, rope, S_TXT, S_IMG, 1.0f);

    // attention
    cudaFuncSetAttribute(attn_k, cudaFuncAttributeMaxDynamicSharedMemorySize, AT_SMEM);
    attn_k<<<dim3(S_TOT / 128, NH), 256, AT_SMEM>>>(q, k, v, oh, ol);

    // output projections: hid (image rows, joint offset 512) then enc (text rows)
    hsgemm_k<0><<<dim3(3072 / 128, S_IMG / 128), 256, GS_BYTES>>>(oh, ol, 3072, S_TXT, wouth, woutl, bout, out, 3072, 3072, 0);
    hsgemm_k<0><<<dim3(3072 / 128, S_TXT / 128), 256, GS_BYTES>>>(oh, ol, 3072, 0, waouth, waoutl, baout, out + (size_t)S_IMG * 3072, 3072, 3072, 0);
}

// round 6
// speedup vs baseline: 5.6811x; 1.1451x over previous
#include <cuda_runtime.h>
#include <cuda_fp16.h>
#include <cstdint>
#include <math.h>

#define S_IMG 4096
#define S_TXT 512
#define S_TOT 4608
#define D_MODEL 3072
#define NH 24
#define NKV 8
#define HD 128

// ---------------- scratch buffers ----------------
__device__ __align__(16) __half g_hsh[S_IMG * D_MODEL];
__device__ __align__(16) __half g_hsl[S_IMG * D_MODEL];
__device__ __align__(16) __half g_ehsh[S_TXT * D_MODEL];
__device__ __align__(16) __half g_ehsl[S_TXT * D_MODEL];
// weights: fp16 hi only
__device__ __align__(16) __half g_wq[D_MODEL * 3072];
__device__ __align__(16) __half g_wk[D_MODEL * 1024];
__device__ __align__(16) __half g_wv[D_MODEL * 1024];
__device__ __align__(16) __half g_awq[D_MODEL * 3072];
__device__ __align__(16) __half g_awk[D_MODEL * 1024];
__device__ __align__(16) __half g_awv[D_MODEL * 1024];
__device__ __align__(16) __half g_wout[3072 * D_MODEL];
__device__ __align__(16) __half g_waout[3072 * D_MODEL];
__device__ __align__(16) float g_qf[NH * S_TOT * HD];
__device__ __align__(16) float g_kf[NKV * S_TOT * HD];
__device__ __align__(16) __half g_qh[NH * S_TOT * HD];
__device__ __align__(16) __half g_ql[NH * S_TOT * HD];
__device__ __align__(16) __half g_k[NKV * S_TOT * HD];
__device__ __align__(16) __half g_v[NKV * S_TOT * HD];
__device__ __align__(16) __half g_oh[S_TOT * 3072];
__device__ __align__(16) __half g_ol[S_TOT * 3072];

// ---------------- PTX helpers ----------------
__device__ __forceinline__ uint32_t cvta_s(const void* p) {
    return (uint32_t)__cvta_generic_to_shared(p);
}
__device__ __forceinline__ void ldsm4(uint32_t* r, uint32_t addr) {
    asm volatile("ldmatrix.sync.aligned.m8n8.x4.shared.b16 {%0,%1,%2,%3},[%4];"
                 : "=r"(r[0]), "=r"(r[1]), "=r"(r[2]), "=r"(r[3]) : "r"(addr));
}
__device__ __forceinline__ void ldsm4t(uint32_t* r, uint32_t addr) {
    asm volatile("ldmatrix.sync.aligned.m8n8.x4.trans.shared.b16 {%0,%1,%2,%3},[%4];"
                 : "=r"(r[0]), "=r"(r[1]), "=r"(r[2]), "=r"(r[3]) : "r"(addr));
}
__device__ __forceinline__ void mma16816(float* c, const uint32_t* a, uint32_t b0, uint32_t b1) {
    asm volatile(
        "mma.sync.aligned.m16n8k16.row.col.f32.f16.f16.f32 "
        "{%0,%1,%2,%3},{%4,%5,%6,%7},{%8,%9},{%0,%1,%2,%3};"
        : "+f"(c[0]), "+f"(c[1]), "+f"(c[2]), "+f"(c[3])
        : "r"(a[0]), "r"(a[1]), "r"(a[2]), "r"(a[3]), "r"(b0), "r"(b1));
}
__device__ __forceinline__ uint32_t packh2(float x, float y) {
    __half2 h = __floats2half2_rn(x, y);
    return *(uint32_t*)&h;
}
__device__ __forceinline__ void cp16(uint32_t s, const void* g) {
    asm volatile("cp.async.cg.shared.global [%0], [%1], 16;" :: "r"(s), "l"(g));
}
__device__ __forceinline__ void cp_commit() {
    asm volatile("cp.async.commit_group;" ::: "memory");
}

// ---------------- fp32 -> split fp16 (hi + lo) ----------------
__global__ void split_k(const float* __restrict__ in, __half* __restrict__ hi,
                        __half* __restrict__ lo, int n) {
    int i = (blockIdx.x * 256 + threadIdx.x) * 4;
    if (i < n) {
        float4 v = *(const float4*)(in + i);
        __half h0 = __float2half_rn(v.x), h1 = __float2half_rn(v.y);
        __half h2 = __float2half_rn(v.z), h3 = __float2half_rn(v.w);
        *(__half2*)(hi + i) = __halves2half2(h0, h1);
        *(__half2*)(hi + i + 2) = __halves2half2(h2, h3);
        *(__half2*)(lo + i) = __floats2half2_rn(v.x - __half2float(h0), v.y - __half2float(h1));
        *(__half2*)(lo + i + 2) = __floats2half2_rn(v.z - __half2float(h2), v.w - __half2float(h3));
    }
}

// ---------------- fp32 -> fp16 (weights, hi only) ----------------
__global__ void f2h_k(const float* __restrict__ in, __half* __restrict__ out, int n) {
    int i = (blockIdx.x * 256 + threadIdx.x) * 4;
    if (i < n) {
        float4 v = *(const float4*)(in + i);
        *(__half2*)(out + i) = __floats2half2_rn(v.x, v.y);
        *(__half2*)(out + i + 2) = __floats2half2_rn(v.z, v.w);
    }
}

// ---------------- 2-term split HGEMM: C = (Ah+Al)@Bh + bias ----------------
// Stage layout (halves): Ah[0,4096) Al[4096,8192) Bh[8192,12288)
#define GS_STAGE 12288
#define GS_BYTES (3 * GS_STAGE * 2)

template<int CMODE>
__global__ __launch_bounds__(256) void hsgemm_k(
    const __half* __restrict__ Ah, const __half* __restrict__ Al, int lda, int arow0,
    const __half* __restrict__ Bh,
    const float* __restrict__ bias, void* __restrict__ Cp, int N, int K, int c_soff)
{
    extern __shared__ __align__(16) __half smp[];
    const int tid = threadIdx.x;
    const int lane = tid & 31, warp = tid >> 5;
    const int m_off = (warp >> 1) * 32, n_off = (warp & 1) * 64;
    const int m0 = blockIdx.y * 128, n0 = blockIdx.x * 128;

    float c[2][8][4];
#pragma unroll
    for (int mi = 0; mi < 2; mi++)
#pragma unroll
        for (int nj = 0; nj < 8; nj++)
#pragma unroll
            for (int t = 0; t < 4; t++) c[mi][nj][t] = 0.f;

    const int t2 = tid + 256;
    const int aR0 = tid >> 2, aC0 = tid & 3, aR1 = t2 >> 2, aC1 = t2 & 3;
    const int bR0 = tid >> 4, bC0 = tid & 15, bR1 = t2 >> 4, bC1 = t2 & 15;
    const size_t aO0 = (size_t)(arow0 + m0 + aR0) * lda + aC0 * 8;
    const size_t aO1 = (size_t)(arow0 + m0 + aR1) * lda + aC1 * 8;
    const size_t bO0 = (size_t)bR0 * N + n0 + bC0 * 8;
    const size_t bO1 = (size_t)bR1 * N + n0 + bC1 * 8;
    const int sA0 = aR0 * 32 + ((aC0 ^ (aR0 & 3)) << 3);
    const int sA1 = aR1 * 32 + ((aC1 ^ (aR1 & 3)) << 3);
    const int sB0 = bR0 * 128 + ((bC0 ^ (bR0 & 7)) << 3);
    const int sB1 = bR1 * 128 + ((bC1 ^ (bR1 & 7)) << 3);

    auto issue = [&](int stage, int k0) {
        __half* st = smp + stage * GS_STAGE;
        uint32_t a0 = cvta_s(st + sA0), a1 = cvta_s(st + sA1);
        cp16(a0, Ah + aO0 + k0);
        cp16(a1, Ah + aO1 + k0);
        cp16(a0 + 8192, Al + aO0 + k0);
        cp16(a1 + 8192, Al + aO1 + k0);
        uint32_t b0 = cvta_s(st + 8192 + sB0), b1 = cvta_s(st + 8192 + sB1);
        size_t ko = (size_t)k0 * N;
        cp16(b0, Bh + bO0 + ko);
        cp16(b1, Bh + bO1 + ko);
    };

    const int nkt = K >> 5;
    issue(0, 0); cp_commit();
    issue(1, 32); cp_commit();

    for (int kt = 0; kt < nkt; kt++) {
        asm volatile("cp.async.wait_group 1;" ::: "memory");
        __syncthreads();
        if (kt + 2 < nkt) issue((kt + 2) % 3, (kt + 2) * 32);
        cp_commit();

        __half* st = smp + (kt % 3) * GS_STAGE;
        __half* Ash = st;
        __half* Asl = st + 4096;
        __half* Bsh = st + 8192;
#pragma unroll
        for (int kk = 0; kk < 2; kk++) {
            uint32_t ah[2][4], al[2][4];
#pragma unroll
            for (int mi = 0; mi < 2; mi++) {
                int row = m_off + mi * 16 + (lane & 15);
                int c8 = kk * 2 + (lane >> 4);
                int off = row * 32 + ((c8 ^ (row & 3)) << 3);
                ldsm4(ah[mi], cvta_s(Ash + off));
                ldsm4(al[mi], cvta_s(Asl + off));
            }
#pragma unroll
            for (int njp = 0; njp < 4; njp++) {
                int row = kk * 16 + (lane & 15);
                int c8 = (n_off >> 3) + njp * 2 + (lane >> 4);
                int off = row * 128 + ((c8 ^ (row & 7)) << 3);
                uint32_t bh[4];
                ldsm4t(bh, cvta_s(Bsh + off));
#pragma unroll
                for (int mi = 0; mi < 2; mi++) {
                    mma16816(c[mi][2 * njp], ah[mi], bh[0], bh[1]);
                    mma16816(c[mi][2 * njp], al[mi], bh[0], bh[1]);
                    mma16816(c[mi][2 * njp + 1], ah[mi], bh[2], bh[3]);
                    mma16816(c[mi][2 * njp + 1], al[mi], bh[2], bh[3]);
                }
            }
        }
    }

#pragma unroll
    for (int mi = 0; mi < 2; mi++) {
#pragma unroll
        for (int nj = 0; nj < 8; nj++) {
            int r0 = m0 + m_off + mi * 16 + (lane >> 2);
            int r1 = r0 + 8;
            int col = n0 + n_off + nj * 8 + ((lane & 3) << 1);
            float bx = bias[col], by = bias[col + 1];
            float v00 = c[mi][nj][0] + bx, v01 = c[mi][nj][1] + by;
            float v10 = c[mi][nj][2] + bx, v11 = c[mi][nj][3] + by;
            if (CMODE == 0) {
                float* C = (float*)Cp;
                *(float2*)(C + (size_t)r0 * N + col) = make_float2(v00, v01);
                *(float2*)(C + (size_t)r1 * N + col) = make_float2(v10, v11);
            } else if (CMODE == 1) {
                __half* C = (__half*)Cp;
                int head = col >> 7, hc = col & 127;
                *(__half2*)(C + ((size_t)head * S_TOT + c_soff + r0) * HD + hc) = __floats2half2_rn(v00, v01);
                *(__half2*)(C + ((size_t)head * S_TOT + c_soff + r1) * HD + hc) = __floats2half2_rn(v10, v11);
            } else {
                float* C = (float*)Cp;
                int head = col >> 7, hc = col & 127;
                *(float2*)(C + ((size_t)head * S_TOT + c_soff + r0) * HD + hc) = make_float2(v00, v01);
                *(float2*)(C + ((size_t)head * S_TOT + c_soff + r1) * HD + hc) = make_float2(v10, v11);
            }
        }
    }
}

// ---------------- fused RMSNorm + RoPE (f32 in; f16 out, optional hi/lo split) ----------------
__global__ void nr_k(const float* __restrict__ in, __half* __restrict__ outh,
                     __half* __restrict__ outl, const float* __restrict__ w,
                     const float* __restrict__ rope, int s0, int scount, float oscale)
{
    int warp = threadIdx.x >> 5, lane = threadIdx.x & 31;
    int idx = blockIdx.x * 4 + warp;
    int h = idx / scount;
    int s = s0 + (idx - h * scount);
    const float* row = in + ((size_t)h * S_TOT + s) * HD;
    size_t obase = ((size_t)h * S_TOT + s) * HD + lane * 4;
    float4 x = *(const float4*)(row + lane * 4);
    float ss = x.x * x.x + x.y * x.y + x.z * x.z + x.w * x.w;
#pragma unroll
    for (int o = 16; o; o >>= 1) ss += __shfl_xor_sync(0xffffffffu, ss, o);
    float r = rsqrtf(ss * (1.0f / HD) + 1e-6f);
    float4 wv = *(const float4*)(w + lane * 4);
    float y0 = x.x * r * wv.x, y1 = x.y * r * wv.y;
    float y2 = x.z * r * wv.z, y3 = x.w * r * wv.w;
    float4 cc = *(const float4*)(rope + (size_t)s * HD + lane * 4);
    float4 sn = *(const float4*)(rope + (size_t)S_TOT * HD + (size_t)s * HD + lane * 4);
    float o0 = (y0 * cc.x - y1 * sn.x) * oscale;
    float o1 = (y1 * cc.y + y0 * sn.y) * oscale;
    float o2 = (y2 * cc.z - y3 * sn.z) * oscale;
    float o3 = (y3 * cc.w + y2 * sn.w) * oscale;
    __half h0 = __float2half_rn(o0), h1 = __float2half_rn(o1);
    __half h2 = __float2half_rn(o2), h3 = __float2half_rn(o3);
    *(__half2*)(outh + obase) = __halves2half2(h0, h1);
    *(__half2*)(outh + obase + 2) = __halves2half2(h2, h3);
    if (outl) {
        *(__half2*)(outl + obase) =
            __floats2half2_rn(o0 - __half2float(h0), o1 - __half2float(h1));
        *(__half2*)(outl + obase + 2) =
            __floats2half2_rn(o2 - __half2float(h2), o3 - __half2float(h3));
    }
}

// ---------------- flash attention: split-q QK^T, 256 thr, 128-row tile ----------------
#define AT_STEPS (S_TOT / 64)
#define AT_SMEM ((16384 + 16384 + 2 * 8192 + 2 * 8192) * 2)

__global__ __launch_bounds__(256) void attn_k(
    const __half* __restrict__ qh, const __half* __restrict__ qlg,
    const __half* __restrict__ kg, const __half* __restrict__ vg,
    __half* __restrict__ oh, __half* __restrict__ ol)
{
    extern __shared__ __align__(16) __half sm[];
    __half* Qh = sm;                  // 128x128
    __half* Ql = sm + 16384;          // 128x128
    __half* Kb = sm + 32768;          // 2 x 64x128
    __half* Vb = sm + 49152;          // 2 x 64x128
    const int tid = threadIdx.x, lane = tid & 31, w = tid >> 5;
    const int h = blockIdx.y, m0 = blockIdx.x * 128;
    const int kvh = h / 3;

    const __half* qbh = qh + ((size_t)h * S_TOT + m0) * HD;
    const __half* qbl = qlg + ((size_t)h * S_TOT + m0) * HD;
#pragma unroll
    for (int t = 0; t < 8; t++) {
        int cid = tid + t * 256;
        int r = cid >> 4, c8 = cid & 15;
        int off = r * 128 + ((c8 ^ (r & 7)) << 3);
        cp16(cvta_s(Qh + off), qbh + (size_t)r * HD + c8 * 8);
        cp16(cvta_s(Ql + off), qbl + (size_t)r * HD + c8 * 8);
    }

    const __half* kb0 = kg + (size_t)kvh * S_TOT * HD;
    const __half* vb0 = vg + (size_t)kvh * S_TOT * HD;
    auto issue_kv = [&](int n, int buf) {
        const __half* kb = kb0 + (size_t)n * 64 * HD;
        const __half* vb = vb0 + (size_t)n * 64 * HD;
        __half* Kd = Kb + buf * 8192;
        __half* Vd = Vb + buf * 8192;
#pragma unroll
        for (int t = 0; t < 4; t++) {
            int cid = tid + t * 256;
            int r = cid >> 4, c8 = cid & 15;
            int off = r * 128 + ((c8 ^ (r & 7)) << 3);
            cp16(cvta_s(Kd + off), kb + (size_t)r * HD + c8 * 8);
            cp16(cvta_s(Vd + off), vb + (size_t)r * HD + c8 * 8);
        }
    };
    issue_kv(0, 0);
    cp_commit();

    float oa[16][4];
#pragma unroll
    for (int nj = 0; nj < 16; nj++)
#pragma unroll
        for (int t = 0; t < 4; t++) oa[nj][t] = 0.f;
    float mI0 = -INFINITY, mI1 = -INFINITY, lI0 = 0.f, lI1 = 0.f;

    for (int it = 0; it < AT_STEPS; it++) {
        asm volatile("cp.async.wait_group 0;" ::: "memory");
        __syncthreads();
        if (it + 1 < AT_STEPS) issue_kv(it + 1, (it + 1) & 1);
        cp_commit();
        __half* Ks = Kb + (it & 1) * 8192;
        __half* Vs = Vb + (it & 1) * 8192;

        float s[8][4];
#pragma unroll
        for (int j = 0; j < 8; j++)
#pragma unroll
            for (int t = 0; t < 4; t++) s[j][t] = 0.f;

#pragma unroll
        for (int dk = 0; dk < 8; dk++) {
            uint32_t a[4], al[4];
            {
                int row = w * 16 + (lane & 15);
                int c8 = dk * 2 + (lane >> 4);
                int off = row * 128 + ((c8 ^ (row & 7)) << 3);
                ldsm4(a, cvta_s(Qh + off));
                ldsm4(al, cvta_s(Ql + off));
            }
#pragma unroll
            for (int njp = 0; njp < 4; njp++) {
                int row = njp * 16 + (lane & 7) + ((lane >> 4) << 3);
                int c8 = dk * 2 + ((lane >> 3) & 1);
                uint32_t b[4];
                ldsm4(b, cvta_s(Ks + row * 128 + ((c8 ^ (row & 7)) << 3)));
                mma16816(s[2 * njp], a, b[0], b[1]);
                mma16816(s[2 * njp], al, b[0], b[1]);
                mma16816(s[2 * njp + 1], a, b[2], b[3]);
                mma16816(s[2 * njp + 1], al, b[2], b[3]);
            }
        }

        float mx0 = -INFINITY, mx1 = -INFINITY;
#pragma unroll
        for (int j = 0; j < 8; j++) {
            mx0 = fmaxf(mx0, fmaxf(s[j][0], s[j][1]));
            mx1 = fmaxf(mx1, fmaxf(s[j][2], s[j][3]));
        }
        mx0 = fmaxf(mx0, __shfl_xor_sync(0xffffffffu, mx0, 1));
        mx0 = fmaxf(mx0, __shfl_xor_sync(0xffffffffu, mx0, 2));
        mx1 = fmaxf(mx1, __shfl_xor_sync(0xffffffffu, mx1, 1));
        mx1 = fmaxf(mx1, __shfl_xor_sync(0xffffffffu, mx1, 2));
        float mn0 = fmaxf(mI0, mx0), mn1 = fmaxf(mI1, mx1);
        float al0 = exp2f(mI0 - mn0), al1 = exp2f(mI1 - mn1);
        mI0 = mn0; mI1 = mn1;
        float rs0 = 0.f, rs1 = 0.f;
#pragma unroll
        for (int j = 0; j < 8; j++) {
            s[j][0] = exp2f(s[j][0] - mn0);
            s[j][1] = exp2f(s[j][1] - mn0);
            s[j][2] = exp2f(s[j][2] - mn1);
            s[j][3] = exp2f(s[j][3] - mn1);
            rs0 += s[j][0] + s[j][1];
            rs1 += s[j][2] + s[j][3];
        }
        rs0 += __shfl_xor_sync(0xffffffffu, rs0, 1);
        rs0 += __shfl_xor_sync(0xffffffffu, rs0, 2);
        rs1 += __shfl_xor_sync(0xffffffffu, rs1, 1);
        rs1 += __shfl_xor_sync(0xffffffffu, rs1, 2);
        lI0 = lI0 * al0 + rs0;
        lI1 = lI1 * al1 + rs1;
#pragma unroll
        for (int nj = 0; nj < 16; nj++) {
            oa[nj][0] *= al0; oa[nj][1] *= al0;
            oa[nj][2] *= al1; oa[nj][3] *= al1;
        }
        uint32_t pa[4][4];
#pragma unroll
        for (int kc = 0; kc < 4; kc++) {
            pa[kc][0] = packh2(s[2 * kc][0], s[2 * kc][1]);
            pa[kc][1] = packh2(s[2 * kc][2], s[2 * kc][3]);
            pa[kc][2] = packh2(s[2 * kc + 1][0], s[2 * kc + 1][1]);
            pa[kc][3] = packh2(s[2 * kc + 1][2], s[2 * kc + 1][3]);
        }
#pragma unroll
        for (int kc = 0; kc < 4; kc++) {
#pragma unroll
            for (int njp = 0; njp < 8; njp++) {
                int row = kc * 16 + (lane & 15);
                int c8 = njp * 2 + (lane >> 4);
                uint32_t b[4];
                ldsm4t(b, cvta_s(Vs + row * 128 + ((c8 ^ (row & 7)) << 3)));
                mma16816(oa[2 * njp], pa[kc], b[0], b[1]);
                mma16816(oa[2 * njp + 1], pa[kc], b[2], b[3]);
            }
        }
    }

    float inv0 = 1.f / lI0, inv1 = 1.f / lI1;
    int gr0 = m0 + w * 16 + (lane >> 2);
    int gr1 = gr0 + 8;
#pragma unroll
    for (int nj = 0; nj < 16; nj++) {
        int col = h * 128 + nj * 8 + ((lane & 3) << 1);
        float v00 = oa[nj][0] * inv0, v01 = oa[nj][1] * inv0;
        float v10 = oa[nj][2] * inv1, v11 = oa[nj][3] * inv1;
        __half h00 = __float2half_rn(v00), h01 = __float2half_rn(v01);
        __half h10 = __float2half_rn(v10), h11 = __float2half_rn(v11);
        *(__half2*)(oh + (size_t)gr0 * 3072 + col) = __halves2half2(h00, h01);
        *(__half2*)(oh + (size_t)gr1 * 3072 + col) = __halves2half2(h10, h11);
        *(__half2*)(ol + (size_t)gr0 * 3072 + col) =
            __floats2half2_rn(v00 - __half2float(h00), v01 - __half2float(h01));
        *(__half2*)(ol + (size_t)gr1 * 3072 + col) =
            __floats2half2_rn(v10 - __half2float(h10), v11 - __half2float(h11));
    }
}

// ---------------- launch ----------------
extern "C" void kernel_launch(void* const* d_in, const int* in_sizes, int n_in,
                              void* d_out, int out_size)
{
    const float* hs    = (const float*)d_in[0];
    const float* ehs   = (const float*)d_in[1];
    const float* rope  = (const float*)d_in[2];
    const float* Wq    = (const float*)d_in[3];
    const float* bq    = (const float*)d_in[4];
    const float* Wk    = (const float*)d_in[5];
    const float* bk    = (const float*)d_in[6];
    const float* Wv    = (const float*)d_in[7];
    const float* bv    = (const float*)d_in[8];
    const float* aWq   = (const float*)d_in[9];
    const float* abq   = (const float*)d_in[10];
    const float* aWk   = (const float*)d_in[11];
    const float* abk   = (const float*)d_in[12];
    const float* aWv   = (const float*)d_in[13];
    const float* abv   = (const float*)d_in[14];
    const float* nq    = (const float*)d_in[15];
    const float* nk    = (const float*)d_in[16];
    const float* anq   = (const float*)d_in[17];
    const float* ank   = (const float*)d_in[18];
    const float* Wout  = (const float*)d_in[19];
    const float* bout  = (const float*)d_in[20];
    const float* Waout = (const float*)d_in[21];
    const float* baout = (const float*)d_in[22];
    float* out = (float*)d_out;

    __half *hsh, *hsl, *ehsh, *ehsl;
    __half *wq, *wk, *wv, *awq, *awk, *awv, *wout, *waout;
    float *qf, *kf;
    __half *qhb, *qlb, *k, *v, *oh, *ol;
    cudaGetSymbolAddress((void**)&hsh, g_hsh);
    cudaGetSymbolAddress((void**)&hsl, g_hsl);
    cudaGetSymbolAddress((void**)&ehsh, g_ehsh);
    cudaGetSymbolAddress((void**)&ehsl, g_ehsl);
    cudaGetSymbolAddress((void**)&wq, g_wq);
    cudaGetSymbolAddress((void**)&wk, g_wk);
    cudaGetSymbolAddress((void**)&wv, g_wv);
    cudaGetSymbolAddress((void**)&awq, g_awq);
    cudaGetSymbolAddress((void**)&awk, g_awk);
    cudaGetSymbolAddress((void**)&awv, g_awv);
    cudaGetSymbolAddress((void**)&wout, g_wout);
    cudaGetSymbolAddress((void**)&waout, g_waout);
    cudaGetSymbolAddress((void**)&qf, g_qf);
    cudaGetSymbolAddress((void**)&kf, g_kf);
    cudaGetSymbolAddress((void**)&qhb, g_qh);
    cudaGetSymbolAddress((void**)&qlb, g_ql);
    cudaGetSymbolAddress((void**)&k, g_k);
    cudaGetSymbolAddress((void**)&v, g_v);
    cudaGetSymbolAddress((void**)&oh, g_oh);
    cudaGetSymbolAddress((void**)&ol, g_ol);

    // activations: split hi/lo
    split_k<<<(S_IMG * D_MODEL) / 1024, 256>>>(hs, hsh, hsl, S_IMG * D_MODEL);
    split_k<<<(S_TXT * D_MODEL) / 1024, 256>>>(ehs, ehsh, ehsl, S_TXT * D_MODEL);
    // weights: hi only
    f2h_k<<<(D_MODEL * 3072) / 1024, 256>>>(Wq, wq, D_MODEL * 3072);
    f2h_k<<<(D_MODEL * 1024) / 1024, 256>>>(Wk, wk, D_MODEL * 1024);
    f2h_k<<<(D_MODEL * 1024) / 1024, 256>>>(Wv, wv, D_MODEL * 1024);
    f2h_k<<<(D_MODEL * 3072) / 1024, 256>>>(aWq, awq, D_MODEL * 3072);
    f2h_k<<<(D_MODEL * 1024) / 1024, 256>>>(aWk, awk, D_MODEL * 1024);
    f2h_k<<<(D_MODEL * 1024) / 1024, 256>>>(aWv, awv, D_MODEL * 1024);
    f2h_k<<<(3072 * D_MODEL) / 1024, 256>>>(Wout, wout, 3072 * D_MODEL);
    f2h_k<<<(3072 * D_MODEL) / 1024, 256>>>(Waout, waout, 3072 * D_MODEL);

    cudaFuncSetAttribute(hsgemm_k<0>, cudaFuncAttributeMaxDynamicSharedMemorySize, GS_BYTES);
    cudaFuncSetAttribute(hsgemm_k<1>, cudaFuncAttributeMaxDynamicSharedMemorySize, GS_BYTES);
    cudaFuncSetAttribute(hsgemm_k<2>, cudaFuncAttributeMaxDynamicSharedMemorySize, GS_BYTES);

    // projections (image rows -> joint offset 512; text rows -> 0)
    hsgemm_k<2><<<dim3(3072 / 128, S_IMG / 128), 256, GS_BYTES>>>(hsh, hsl, D_MODEL, 0, wq, bq, qf, 3072, D_MODEL, S_TXT);
    hsgemm_k<2><<<dim3(1024 / 128, S_IMG / 128), 256, GS_BYTES>>>(hsh, hsl, D_MODEL, 0, wk, bk, kf, 1024, D_MODEL, S_TXT);
    hsgemm_k<1><<<dim3(1024 / 128, S_IMG / 128), 256, GS_BYTES>>>(hsh, hsl, D_MODEL, 0, wv, bv, v, 1024, D_MODEL, S_TXT);
    hsgemm_k<2><<<dim3(3072 / 128, S_TXT / 128), 256, GS_BYTES>>>(ehsh, ehsl, D_MODEL, 0, awq, abq, qf, 3072, D_MODEL, 0);
    hsgemm_k<2><<<dim3(1024 / 128, S_TXT / 128), 256, GS_BYTES>>>(ehsh, ehsl, D_MODEL, 0, awk, abk, kf, 1024, D_MODEL, 0);
    hsgemm_k<1><<<dim3(1024 / 128, S_TXT / 128), 256, GS_BYTES>>>(ehsh, ehsl, D_MODEL, 0, awv, abv, v, 1024, D_MODEL, 0);

    // RMSNorm + RoPE; Q split into hi/lo, fold softmax scale * log2(e) into Q
    const float qscale = 0.08838834764831845f * 1.4426950408889634f;
    nr_k<<<(NH * S_TXT) / 4, 128>>>(qf, qhb, qlb, anq, rope, 0, S_TXT, qscale);
    nr_k<<<(NH * S_IMG) / 4, 128>>>(qf, qhb, qlb, nq, rope, S_TXT, S_IMG, qscale);
    nr_k<<<(NKV * S_TXT) / 4, 128>>>(kf, k, ((__half*)0), ank, rope, 0, S_TXT, 1.0f);
    nr_k<<<(NKV * S_IMG) / 4, 128>>>(kf, k, ((__half*)0), nk, rope, S_TXT, S_IMG, 1.0f);

    // attention
    cudaFuncSetAttribute(attn_k, cudaFuncAttributeMaxDynamicSharedMemorySize, AT_SMEM);
    attn_k<<<dim3(S_TOT / 128, NH), 256, AT_SMEM>>>(qhb, qlb, k, v, oh, ol);

    // output projections: hid (image rows, joint offset 512) then enc (text rows)
    hsgemm_k<0><<<dim3(3072 / 128, S_IMG / 128), 256, GS_BYTES>>>(oh, ol, 3072, S_TXT, wout, bout, out, 3072, 3072, 0);
    hsgemm_k<0><<<dim3(3072 / 128, S_TXT / 128), 256, GS_BYTES>>>(oh, ol, 3072, 0, waout, baout, out + (size_t)S_IMG * 3072, 3072, 3072, 0);
}

// round 8
// speedup vs baseline: 7.1239x; 1.2540x over previous
#include <cuda_runtime.h>
#include <cuda_fp16.h>
#include <cstdint>
#include <math.h>

#define S_IMG 4096
#define S_TXT 512
#define S_TOT 4608
#define D_MODEL 3072
#define NH 24
#define NKV 8
#define HD 128

// ---------------- scratch buffers ----------------
__device__ __align__(16) __half g_hsh[S_IMG * D_MODEL];
__device__ __align__(16) __half g_hsl[S_IMG * D_MODEL];
__device__ __align__(16) __half g_ehsh[S_TXT * D_MODEL];
__device__ __align__(16) __half g_ehsl[S_TXT * D_MODEL];
__device__ __align__(16) __half g_wq[D_MODEL * 3072];
__device__ __align__(16) __half g_wk[D_MODEL * 1024];
__device__ __align__(16) __half g_wv[D_MODEL * 1024];
__device__ __align__(16) __half g_awq[D_MODEL * 3072];
__device__ __align__(16) __half g_awk[D_MODEL * 1024];
__device__ __align__(16) __half g_awv[D_MODEL * 1024];
__device__ __align__(16) __half g_wout[3072 * D_MODEL];
__device__ __align__(16) __half g_waout[3072 * D_MODEL];
__device__ __align__(16) float g_qf[NH * S_TOT * HD];
__device__ __align__(16) float g_kf[NKV * S_TOT * HD];
__device__ __align__(16) __half g_qhb[NH * S_TOT * HD];
__device__ __align__(16) __half g_qlb[NH * S_TOT * HD];
__device__ __align__(16) __half g_kb[NKV * S_TOT * HD];
__device__ __align__(16) __half g_vb[NKV * S_TOT * HD];
__device__ __align__(16) __half g_oh[S_TOT * 3072];
__device__ __align__(16) __half g_ol[S_TOT * 3072];

// ---------------- PTX helpers ----------------
__device__ __forceinline__ uint32_t cvta_s(const void* p) {
    return (uint32_t)__cvta_generic_to_shared(p);
}
__device__ __forceinline__ void ldsm4(uint32_t* r, uint32_t addr) {
    asm volatile("ldmatrix.sync.aligned.m8n8.x4.shared.b16 {%0,%1,%2,%3},[%4];"
                 : "=r"(r[0]), "=r"(r[1]), "=r"(r[2]), "=r"(r[3]) : "r"(addr));
}
__device__ __forceinline__ void ldsm4t(uint32_t* r, uint32_t addr) {
    asm volatile("ldmatrix.sync.aligned.m8n8.x4.trans.shared.b16 {%0,%1,%2,%3},[%4];"
                 : "=r"(r[0]), "=r"(r[1]), "=r"(r[2]), "=r"(r[3]) : "r"(addr));
}
__device__ __forceinline__ void mma16816(float* c, const uint32_t* a, uint32_t b0, uint32_t b1) {
    asm volatile(
        "mma.sync.aligned.m16n8k16.row.col.f32.f16.f16.f32 "
        "{%0,%1,%2,%3},{%4,%5,%6,%7},{%8,%9},{%0,%1,%2,%3};"
        : "+f"(c[0]), "+f"(c[1]), "+f"(c[2]), "+f"(c[3])
        : "r"(a[0]), "r"(a[1]), "r"(a[2]), "r"(a[3]), "r"(b0), "r"(b1));
}
__device__ __forceinline__ uint32_t packh2(float x, float y) {
    __half2 h = __floats2half2_rn(x, y);
    return *(uint32_t*)&h;
}
__device__ __forceinline__ void cp16(uint32_t s, const void* g) {
    asm volatile("cp.async.cg.shared.global [%0], [%1], 16;" :: "r"(s), "l"(g));
}
__device__ __forceinline__ void cp_commit() {
    asm volatile("cp.async.commit_group;" ::: "memory");
}

// ---------------- fp32 -> split fp16 ----------------
__global__ void split_k(const float* __restrict__ in, __half* __restrict__ hi,
                        __half* __restrict__ lo, int n) {
    int i = (blockIdx.x * 256 + threadIdx.x) * 4;
    if (i < n) {
        float4 v = *(const float4*)(in + i);
        __half h0 = __float2half_rn(v.x), h1 = __float2half_rn(v.y);
        __half h2 = __float2half_rn(v.z), h3 = __float2half_rn(v.w);
        *(__half2*)(hi + i) = __halves2half2(h0, h1);
        *(__half2*)(hi + i + 2) = __halves2half2(h2, h3);
        *(__half2*)(lo + i) = __floats2half2_rn(v.x - __half2float(h0), v.y - __half2float(h1));
        *(__half2*)(lo + i + 2) = __floats2half2_rn(v.z - __half2float(h2), v.w - __half2float(h3));
    }
}
__global__ void f2h_k(const float* __restrict__ in, __half* __restrict__ out, int n) {
    int i = (blockIdx.x * 256 + threadIdx.x) * 4;
    if (i < n) {
        float4 v = *(const float4*)(in + i);
        *(__half2*)(out + i) = __floats2half2_rn(v.x, v.y);
        *(__half2*)(out + i + 2) = __floats2half2_rn(v.z, v.w);
    }
}

// ---------------- shared 2-term GEMM mainloop (A=(hi+lo), B=hi) ----------------
// Stage layout (halves): Ah[0,4096) Al[4096,8192) Bh[8192,12288)
#define GS_STAGE 12288
#define GS_BYTES (3 * GS_STAGE * 2)

__device__ __forceinline__ void gemm_mainloop(
    const __half* __restrict__ Ah, const __half* __restrict__ Al, int arow0,
    const __half* __restrict__ Bh, int N, int n0,
    __half* smp, float c[2][8][4], int tid)
{
    const int lane = tid & 31, warp = tid >> 5;
    const int m_off = (warp >> 1) * 32, n_off = (warp & 1) * 64;
    const int t2 = tid + 256;
    const int aR0 = tid >> 2, aC0 = tid & 3, aR1 = t2 >> 2, aC1 = t2 & 3;
    const int bR0 = tid >> 4, bC0 = tid & 15, bR1 = t2 >> 4, bC1 = t2 & 15;
    const size_t aO0 = (size_t)(arow0 + aR0) * D_MODEL + aC0 * 8;
    const size_t aO1 = (size_t)(arow0 + aR1) * D_MODEL + aC1 * 8;
    const size_t bO0 = (size_t)bR0 * N + n0 + bC0 * 8;
    const size_t bO1 = (size_t)bR1 * N + n0 + bC1 * 8;
    const int sA0 = aR0 * 32 + ((aC0 ^ (aR0 & 3)) << 3);
    const int sA1 = aR1 * 32 + ((aC1 ^ (aR1 & 3)) << 3);
    const int sB0 = bR0 * 128 + ((bC0 ^ (bR0 & 7)) << 3);
    const int sB1 = bR1 * 128 + ((bC1 ^ (bR1 & 7)) << 3);

    auto issue = [&](int stage, int k0) {
        __half* st = smp + stage * GS_STAGE;
        uint32_t a0 = cvta_s(st + sA0), a1 = cvta_s(st + sA1);
        cp16(a0, Ah + aO0 + k0);
        cp16(a1, Ah + aO1 + k0);
        cp16(a0 + 8192, Al + aO0 + k0);
        cp16(a1 + 8192, Al + aO1 + k0);
        uint32_t b0 = cvta_s(st + 8192 + sB0), b1 = cvta_s(st + 8192 + sB1);
        size_t ko = (size_t)k0 * N;
        cp16(b0, Bh + bO0 + ko);
        cp16(b1, Bh + bO1 + ko);
    };

    const int nkt = D_MODEL >> 5;   // 96
    issue(0, 0); cp_commit();
    issue(1, 32); cp_commit();

    for (int kt = 0; kt < nkt; kt++) {
        asm volatile("cp.async.wait_group 1;" ::: "memory");
        __syncthreads();
        if (kt + 2 < nkt) issue((kt + 2) % 3, (kt + 2) * 32);
        cp_commit();

        __half* st = smp + (kt % 3) * GS_STAGE;
        __half* Ash = st;
        __half* Asl = st + 4096;
        __half* Bsh = st + 8192;
#pragma unroll
        for (int kk = 0; kk < 2; kk++) {
            uint32_t ah[2][4], al[2][4];
#pragma unroll
            for (int mi = 0; mi < 2; mi++) {
                int row = m_off + mi * 16 + (lane & 15);
                int c8 = kk * 2 + (lane >> 4);
                int off = row * 32 + ((c8 ^ (row & 3)) << 3);
                ldsm4(ah[mi], cvta_s(Ash + off));
                ldsm4(al[mi], cvta_s(Asl + off));
            }
#pragma unroll
            for (int njp = 0; njp < 4; njp++) {
                int row = kk * 16 + (lane & 15);
                int c8 = (n_off >> 3) + njp * 2 + (lane >> 4);
                int off = row * 128 + ((c8 ^ (row & 7)) << 3);
                uint32_t bh[4];
                ldsm4t(bh, cvta_s(Bsh + off));
#pragma unroll
                for (int mi = 0; mi < 2; mi++) {
                    mma16816(c[mi][2 * njp], ah[mi], bh[0], bh[1]);
                    mma16816(c[mi][2 * njp], al[mi], bh[0], bh[1]);
                    mma16816(c[mi][2 * njp + 1], ah[mi], bh[2], bh[3]);
                    mma16816(c[mi][2 * njp + 1], al[mi], bh[2], bh[3]);
                }
            }
        }
    }
}

// ---------------- fused QKV projection (both streams, one launch) ----------------
// grid (40, 36): y<4 -> text rows, else image rows; x<24 -> Q, x<32 -> K, else V.
__global__ __launch_bounds__(256) void qkv_k(
    const float* __restrict__ bq, const float* __restrict__ bk, const float* __restrict__ bv,
    const float* __restrict__ abq, const float* __restrict__ abk, const float* __restrict__ abv)
{
    extern __shared__ __align__(16) __half smp[];
    const int tid = threadIdx.x;
    const int lane = tid & 31, warp = tid >> 5;
    const int m_off = (warp >> 1) * 32, n_off = (warp & 1) * 64;
    const int by = blockIdx.y, bx = blockIdx.x;
    const bool txt = by < 4;
    const __half* Ah = txt ? g_ehsh : g_hsh;
    const __half* Al = txt ? g_ehsl : g_hsl;
    const int arow0 = txt ? by * 128 : (by - 4) * 128;
    const int jrow0 = by * 128;
    const int n0g = bx * 128;

    int seg, lc0, Nw;
    const __half* W;
    const float* bias;
    if (n0g < 3072)      { seg = 0; lc0 = n0g;        Nw = 3072; W = txt ? g_awq : g_wq; bias = txt ? abq : bq; }
    else if (n0g < 4096) { seg = 1; lc0 = n0g - 3072; Nw = 1024; W = txt ? g_awk : g_wk; bias = txt ? abk : bk; }
    else                 { seg = 2; lc0 = n0g - 4096; Nw = 1024; W = txt ? g_awv : g_wv; bias = txt ? abv : bv; }

    float c[2][8][4];
#pragma unroll
    for (int mi = 0; mi < 2; mi++)
#pragma unroll
        for (int nj = 0; nj < 8; nj++)
#pragma unroll
            for (int t = 0; t < 4; t++) c[mi][nj][t] = 0.f;

    gemm_mainloop(Ah, Al, arow0, W, Nw, lc0, smp, c, tid);

#pragma unroll
    for (int mi = 0; mi < 2; mi++) {
#pragma unroll
        for (int nj = 0; nj < 8; nj++) {
            int r0 = m_off + mi * 16 + (lane >> 2);
            int r1 = r0 + 8;
            int col = lc0 + n_off + nj * 8 + ((lane & 3) << 1);
            float bx_ = bias[col], by_ = bias[col + 1];
            float v00 = c[mi][nj][0] + bx_, v01 = c[mi][nj][1] + by_;
            float v10 = c[mi][nj][2] + bx_, v11 = c[mi][nj][3] + by_;
            int head = col >> 7, hc = col & 127;
            if (seg == 0) {
                *(float2*)(g_qf + ((size_t)head * S_TOT + jrow0 + r0) * HD + hc) = make_float2(v00, v01);
                *(float2*)(g_qf + ((size_t)head * S_TOT + jrow0 + r1) * HD + hc) = make_float2(v10, v11);
            } else if (seg == 1) {
                *(float2*)(g_kf + ((size_t)head * S_TOT + jrow0 + r0) * HD + hc) = make_float2(v00, v01);
                *(float2*)(g_kf + ((size_t)head * S_TOT + jrow0 + r1) * HD + hc) = make_float2(v10, v11);
            } else {
                *(__half2*)(g_vb + ((size_t)head * S_TOT + jrow0 + r0) * HD + hc) = __floats2half2_rn(v00, v01);
                *(__half2*)(g_vb + ((size_t)head * S_TOT + jrow0 + r1) * HD + hc) = __floats2half2_rn(v10, v11);
            }
        }
    }
}

// ---------------- fused output projections (one launch) ----------------
// grid (24, 36): y<4 -> text rows (C rows 4096+), else image rows (C rows 0+).
__global__ __launch_bounds__(256) void oproj_k(
    const float* __restrict__ bout, const float* __restrict__ baout, float* __restrict__ out)
{
    extern __shared__ __align__(16) __half smp[];
    const int tid = threadIdx.x;
    const int lane = tid & 31, warp = tid >> 5;
    const int m_off = (warp >> 1) * 32, n_off = (warp & 1) * 64;
    const int by = blockIdx.y, bx = blockIdx.x;
    const bool txt = by < 4;
    const int arow0 = by * 128;                         // joint row in g_oh/g_ol
    const int crow0 = txt ? 4096 + by * 128 : by * 128 - 512;
    const __half* W = txt ? g_waout : g_wout;
    const float* bias = txt ? baout : bout;
    const int n0 = bx * 128;

    float c[2][8][4];
#pragma unroll
    for (int mi = 0; mi < 2; mi++)
#pragma unroll
        for (int nj = 0; nj < 8; nj++)
#pragma unroll
            for (int t = 0; t < 4; t++) c[mi][nj][t] = 0.f;

    gemm_mainloop(g_oh, g_ol, arow0, W, 3072, n0, smp, c, tid);

#pragma unroll
    for (int mi = 0; mi < 2; mi++) {
#pragma unroll
        for (int nj = 0; nj < 8; nj++) {
            int r0 = m_off + mi * 16 + (lane >> 2);
            int r1 = r0 + 8;
            int col = n0 + n_off + nj * 8 + ((lane & 3) << 1);
            float bx_ = bias[col], by_ = bias[col + 1];
            *(float2*)(out + (size_t)(crow0 + r0) * 3072 + col) =
                make_float2(c[mi][nj][0] + bx_, c[mi][nj][1] + by_);
            *(float2*)(out + (size_t)(crow0 + r1) * 3072 + col) =
                make_float2(c[mi][nj][2] + bx_, c[mi][nj][3] + by_);
        }
    }
}

// ---------------- fused RMSNorm + RoPE ----------------
__global__ void nr_k(const float* __restrict__ in, __half* __restrict__ outh,
                     __half* __restrict__ outl, const float* __restrict__ w,
                     const float* __restrict__ rope, int s0, int scount, float oscale)
{
    int warp = threadIdx.x >> 5, lane = threadIdx.x & 31;
    int idx = blockIdx.x * 4 + warp;
    int h = idx / scount;
    int s = s0 + (idx - h * scount);
    const float* row = in + ((size_t)h * S_TOT + s) * HD;
    size_t obase = ((size_t)h * S_TOT + s) * HD + lane * 4;
    float4 x = *(const float4*)(row + lane * 4);
    float ss = x.x * x.x + x.y * x.y + x.z * x.z + x.w * x.w;
#pragma unroll
    for (int o = 16; o; o >>= 1) ss += __shfl_xor_sync(0xffffffffu, ss, o);
    float r = rsqrtf(ss * (1.0f / HD) + 1e-6f);
    float4 wv = *(const float4*)(w + lane * 4);
    float y0 = x.x * r * wv.x, y1 = x.y * r * wv.y;
    float y2 = x.z * r * wv.z, y3 = x.w * r * wv.w;
    float4 cc = *(const float4*)(rope + (size_t)s * HD + lane * 4);
    float4 sn = *(const float4*)(rope + (size_t)S_TOT * HD + (size_t)s * HD + lane * 4);
    float o0 = (y0 * cc.x - y1 * sn.x) * oscale;
    float o1 = (y1 * cc.y + y0 * sn.y) * oscale;
    float o2 = (y2 * cc.z - y3 * sn.z) * oscale;
    float o3 = (y3 * cc.w + y2 * sn.w) * oscale;
    __half h0 = __float2half_rn(o0), h1 = __float2half_rn(o1);
    __half h2 = __float2half_rn(o2), h3 = __float2half_rn(o3);
    *(__half2*)(outh + obase) = __halves2half2(h0, h1);
    *(__half2*)(outh + obase + 2) = __halves2half2(h2, h3);
    if (outl) {
        *(__half2*)(outl + obase) =
            __floats2half2_rn(o0 - __half2float(h0), o1 - __half2float(h1));
        *(__half2*)(outl + obase + 2) =
            __floats2half2_rn(o2 - __half2float(h2), o3 - __half2float(h3));
    }
}

// ---------------- flash attention: split-q QK^T, 256 thr, 128-row tile ----------------
#define AT_STEPS (S_TOT / 64)
#define AT_SMEM ((16384 + 16384 + 2 * 8192 + 2 * 8192) * 2)

__global__ __launch_bounds__(256) void attn_k(
    const __half* __restrict__ qh, const __half* __restrict__ qlg,
    const __half* __restrict__ kg, const __half* __restrict__ vg,
    __half* __restrict__ oh, __half* __restrict__ ol)
{
    extern __shared__ __align__(16) __half sm[];
    __half* Qh = sm;
    __half* Ql = sm + 16384;
    __half* Kb = sm + 32768;
    __half* Vb = sm + 49152;
    const int tid = threadIdx.x, lane = tid & 31, w = tid >> 5;
    const int h = blockIdx.y, m0 = blockIdx.x * 128;
    const int kvh = h / 3;

    const __half* qbh = qh + ((size_t)h * S_TOT + m0) * HD;
    const __half* qbl = qlg + ((size_t)h * S_TOT + m0) * HD;
#pragma unroll
    for (int t = 0; t < 8; t++) {
        int cid = tid + t * 256;
        int r = cid >> 4, c8 = cid & 15;
        int off = r * 128 + ((c8 ^ (r & 7)) << 3);
        cp16(cvta_s(Qh + off), qbh + (size_t)r * HD + c8 * 8);
        cp16(cvta_s(Ql + off), qbl + (size_t)r * HD + c8 * 8);
    }

    const __half* kb0 = kg + (size_t)kvh * S_TOT * HD;
    const __half* vb0 = vg + (size_t)kvh * S_TOT * HD;
    auto issue_kv = [&](int n, int buf) {
        const __half* kb = kb0 + (size_t)n * 64 * HD;
        const __half* vb = vb0 + (size_t)n * 64 * HD;
        __half* Kd = Kb + buf * 8192;
        __half* Vd = Vb + buf * 8192;
#pragma unroll
        for (int t = 0; t < 4; t++) {
            int cid = tid + t * 256;
            int r = cid >> 4, c8 = cid & 15;
            int off = r * 128 + ((c8 ^ (r & 7)) << 3);
            cp16(cvta_s(Kd + off), kb + (size_t)r * HD + c8 * 8);
            cp16(cvta_s(Vd + off), vb + (size_t)r * HD + c8 * 8);
        }
    };
    issue_kv(0, 0);
    cp_commit();

    float oa[16][4];
#pragma unroll
    for (int nj = 0; nj < 16; nj++)
#pragma unroll
        for (int t = 0; t < 4; t++) oa[nj][t] = 0.f;
    float mI0 = -INFINITY, mI1 = -INFINITY, lI0 = 0.f, lI1 = 0.f;

    for (int it = 0; it < AT_STEPS; it++) {
        asm volatile("cp.async.wait_group 0;" ::: "memory");
        __syncthreads();
        if (it + 1 < AT_STEPS) issue_kv(it + 1, (it + 1) & 1);
        cp_commit();
        __half* Ks = Kb + (it & 1) * 8192;
        __half* Vs = Vb + (it & 1) * 8192;

        float s[8][4];
#pragma unroll
        for (int j = 0; j < 8; j++)
#pragma unroll
            for (int t = 0; t < 4; t++) s[j][t] = 0.f;

#pragma unroll
        for (int dk = 0; dk < 8; dk++) {
            uint32_t a[4], al[4];
            {
                int row = w * 16 + (lane & 15);
                int c8 = dk * 2 + (lane >> 4);
                int off = row * 128 + ((c8 ^ (row & 7)) << 3);
                ldsm4(a, cvta_s(Qh + off));
                ldsm4(al, cvta_s(Ql + off));
            }
#pragma unroll
            for (int njp = 0; njp < 4; njp++) {
                int row = njp * 16 + (lane & 7) + ((lane >> 4) << 3);
                int c8 = dk * 2 + ((lane >> 3) & 1);
                uint32_t b[4];
                ldsm4(b, cvta_s(Ks + row * 128 + ((c8 ^ (row & 7)) << 3)));
                mma16816(s[2 * njp], a, b[0], b[1]);
                mma16816(s[2 * njp], al, b[0], b[1]);
                mma16816(s[2 * njp + 1], a, b[2], b[3]);
                mma16816(s[2 * njp + 1], al, b[2], b[3]);
            }
        }

        float mx0 = -INFINITY, mx1 = -INFINITY;
#pragma unroll
        for (int j = 0; j < 8; j++) {
            mx0 = fmaxf(mx0, fmaxf(s[j][0], s[j][1]));
            mx1 = fmaxf(mx1, fmaxf(s[j][2], s[j][3]));
        }
        mx0 = fmaxf(mx0, __shfl_xor_sync(0xffffffffu, mx0, 1));
        mx0 = fmaxf(mx0, __shfl_xor_sync(0xffffffffu, mx0, 2));
        mx1 = fmaxf(mx1, __shfl_xor_sync(0xffffffffu, mx1, 1));
        mx1 = fmaxf(mx1, __shfl_xor_sync(0xffffffffu, mx1, 2));
        float mn0 = fmaxf(mI0, mx0), mn1 = fmaxf(mI1, mx1);
        float al0 = exp2f(mI0 - mn0), al1 = exp2f(mI1 - mn1);
        mI0 = mn0; mI1 = mn1;
        float rs0 = 0.f, rs1 = 0.f;
#pragma unroll
        for (int j = 0; j < 8; j++) {
            s[j][0] = exp2f(s[j][0] - mn0);
            s[j][1] = exp2f(s[j][1] - mn0);
            s[j][2] = exp2f(s[j][2] - mn1);
            s[j][3] = exp2f(s[j][3] - mn1);
            rs0 += s[j][0] + s[j][1];
            rs1 += s[j][2] + s[j][3];
        }
        rs0 += __shfl_xor_sync(0xffffffffu, rs0, 1);
        rs0 += __shfl_xor_sync(0xffffffffu, rs0, 2);
        rs1 += __shfl_xor_sync(0xffffffffu, rs1, 1);
        rs1 += __shfl_xor_sync(0xffffffffu, rs1, 2);
        lI0 = lI0 * al0 + rs0;
        lI1 = lI1 * al1 + rs1;
#pragma unroll
        for (int nj = 0; nj < 16; nj++) {
            oa[nj][0] *= al0; oa[nj][1] *= al0;
            oa[nj][2] *= al1; oa[nj][3] *= al1;
        }
        uint32_t pa[4][4];
#pragma unroll
        for (int kc = 0; kc < 4; kc++) {
            pa[kc][0] = packh2(s[2 * kc][0], s[2 * kc][1]);
            pa[kc][1] = packh2(s[2 * kc][2], s[2 * kc][3]);
            pa[kc][2] = packh2(s[2 * kc + 1][0], s[2 * kc + 1][1]);
            pa[kc][3] = packh2(s[2 * kc + 1][2], s[2 * kc + 1][3]);
        }
#pragma unroll
        for (int kc = 0; kc < 4; kc++) {
#pragma unroll
            for (int njp = 0; njp < 8; njp++) {
                int row = kc * 16 + (lane & 15);
                int c8 = njp * 2 + (lane >> 4);
                uint32_t b[4];
                ldsm4t(b, cvta_s(Vs + row * 128 + ((c8 ^ (row & 7)) << 3)));
                mma16816(oa[2 * njp], pa[kc], b[0], b[1]);
                mma16816(oa[2 * njp + 1], pa[kc], b[2], b[3]);
            }
        }
    }

    float inv0 = 1.f / lI0, inv1 = 1.f / lI1;
    int gr0 = m0 + w * 16 + (lane >> 2);
    int gr1 = gr0 + 8;
#pragma unroll
    for (int nj = 0; nj < 16; nj++) {
        int col = h * 128 + nj * 8 + ((lane & 3) << 1);
        float v00 = oa[nj][0] * inv0, v01 = oa[nj][1] * inv0;
        float v10 = oa[nj][2] * inv1, v11 = oa[nj][3] * inv1;
        __half h00 = __float2half_rn(v00), h01 = __float2half_rn(v01);
        __half h10 = __float2half_rn(v10), h11 = __float2half_rn(v11);
        *(__half2*)(oh + (size_t)gr0 * 3072 + col) = __halves2half2(h00, h01);
        *(__half2*)(oh + (size_t)gr1 * 3072 + col) = __halves2half2(h10, h11);
        *(__half2*)(ol + (size_t)gr0 * 3072 + col) =
            __floats2half2_rn(v00 - __half2float(h00), v01 - __half2float(h01));
        *(__half2*)(ol + (size_t)gr1 * 3072 + col) =
            __floats2half2_rn(v10 - __half2float(h10), v11 - __half2float(h11));
    }
}

// ---------------- launch ----------------
extern "C" void kernel_launch(void* const* d_in, const int* in_sizes, int n_in,
                              void* d_out, int out_size)
{
    const float* hs    = (const float*)d_in[0];
    const float* ehs   = (const float*)d_in[1];
    const float* rope  = (const float*)d_in[2];
    const float* Wq    = (const float*)d_in[3];
    const float* bq    = (const float*)d_in[4];
    const float* Wk    = (const float*)d_in[5];
    const float* bk    = (const float*)d_in[6];
    const float* Wv    = (const float*)d_in[7];
    const float* bv    = (const float*)d_in[8];
    const float* aWq   = (const float*)d_in[9];
    const float* abq   = (const float*)d_in[10];
    const float* aWk   = (const float*)d_in[11];
    const float* abk   = (const float*)d_in[12];
    const float* aWv   = (const float*)d_in[13];
    const float* abv   = (const float*)d_in[14];
    const float* nq    = (const float*)d_in[15];
    const float* nk    = (const float*)d_in[16];
    const float* anq   = (const float*)d_in[17];
    const float* ank   = (const float*)d_in[18];
    const float* Wout  = (const float*)d_in[19];
    const float* bout  = (const float*)d_in[20];
    const float* Waout = (const float*)d_in[21];
    const float* baout = (const float*)d_in[22];
    float* out = (float*)d_out;

    __half *hsh, *hsl, *ehsh, *ehsl;
    __half *wq, *wk, *wv, *awq, *awk, *awv, *wout, *waout;
    float *qf, *kf;
    __half *qhb, *qlb, *k, *v, *oh, *ol;
    cudaGetSymbolAddress((void**)&hsh, g_hsh);
    cudaGetSymbolAddress((void**)&hsl, g_hsl);
    cudaGetSymbolAddress((void**)&ehsh, g_ehsh);
    cudaGetSymbolAddress((void**)&ehsl, g_ehsl);
    cudaGetSymbolAddress((void**)&wq, g_wq);
    cudaGetSymbolAddress((void**)&wk, g_wk);
    cudaGetSymbolAddress((void**)&wv, g_wv);
    cudaGetSymbolAddress((void**)&awq, g_awq);
    cudaGetSymbolAddress((void**)&awk, g_awk);
    cudaGetSymbolAddress((void**)&awv, g_awv);
    cudaGetSymbolAddress((void**)&wout, g_wout);
    cudaGetSymbolAddress((void**)&waout, g_waout);
    cudaGetSymbolAddress((void**)&qf, g_qf);
    cudaGetSymbolAddress((void**)&kf, g_kf);
    cudaGetSymbolAddress((void**)&qhb, g_qhb);
    cudaGetSymbolAddress((void**)&qlb, g_qlb);
    cudaGetSymbolAddress((void**)&k, g_kb);
    cudaGetSymbolAddress((void**)&v, g_vb);
    cudaGetSymbolAddress((void**)&oh, g_oh);
    cudaGetSymbolAddress((void**)&ol, g_ol);

    // activations: split hi/lo
    split_k<<<(S_IMG * D_MODEL) / 1024, 256>>>(hs, hsh, hsl, S_IMG * D_MODEL);
    split_k<<<(S_TXT * D_MODEL) / 1024, 256>>>(ehs, ehsh, ehsl, S_TXT * D_MODEL);
    // weights: hi only
    f2h_k<<<(D_MODEL * 3072) / 1024, 256>>>(Wq, wq, D_MODEL * 3072);
    f2h_k<<<(D_MODEL * 1024) / 1024, 256>>>(Wk, wk, D_MODEL * 1024);
    f2h_k<<<(D_MODEL * 1024) / 1024, 256>>>(Wv, wv, D_MODEL * 1024);
    f2h_k<<<(D_MODEL * 3072) / 1024, 256>>>(aWq, awq, D_MODEL * 3072);
    f2h_k<<<(D_MODEL * 1024) / 1024, 256>>>(aWk, awk, D_MODEL * 1024);
    f2h_k<<<(D_MODEL * 1024) / 1024, 256>>>(aWv, awv, D_MODEL * 1024);
    f2h_k<<<(3072 * D_MODEL) / 1024, 256>>>(Wout, wout, 3072 * D_MODEL);
    f2h_k<<<(3072 * D_MODEL) / 1024, 256>>>(Waout, waout, 3072 * D_MODEL);

    cudaFuncSetAttribute(qkv_k, cudaFuncAttributeMaxDynamicSharedMemorySize, GS_BYTES);
    cudaFuncSetAttribute(oproj_k, cudaFuncAttributeMaxDynamicSharedMemorySize, GS_BYTES);

    // fused QKV projections: one launch for both streams and all three outputs
    qkv_k<<<dim3(40, 36), 256, GS_BYTES>>>(bq, bk, bv, abq, abk, abv);

    // RMSNorm + RoPE; Q split into hi/lo, fold softmax scale * log2(e) into Q
    const float qscale = 0.08838834764831845f * 1.4426950408889634f;
    nr_k<<<(NH * S_TXT) / 4, 128>>>(qf, qhb, qlb, anq, rope, 0, S_TXT, qscale);
    nr_k<<<(NH * S_IMG) / 4, 128>>>(qf, qhb, qlb, nq, rope, S_TXT, S_IMG, qscale);
    nr_k<<<(NKV * S_TXT) / 4, 128>>>(kf, k, ((__half*)0), ank, rope, 0, S_TXT, 1.0f);
    nr_k<<<(NKV * S_IMG) / 4, 128>>>(kf, k, ((__half*)0), nk, rope, S_TXT, S_IMG, 1.0f);

    // attention
    cudaFuncSetAttribute(attn_k, cudaFuncAttributeMaxDynamicSharedMemorySize, AT_SMEM);
    attn_k<<<dim3(S_TOT / 128, NH), 256, AT_SMEM>>>(qhb, qlb, k, v, oh, ol);

    // fused output projections: one launch for hid + enc
    oproj_k<<<dim3(24, 36), 256, GS_BYTES>>>(bout, baout, out);
}